// round 7
// baseline (speedup 1.0000x reference)
#include <cuda_runtime.h>
#include <stdint.h>
#include <math.h>

// ===== problem dims =====
#define Bdim 512
#define Tdim 256
#define Hdim 512
#define NCdim 512
#define SKELdim 256
#define GENdim 16

#define NBLK 128
#define NTHR 512

typedef unsigned long long ull;

// dynamic smem (floats):
// GRU: sA0 [2][8][32]=512 | sA1 512 | sB0 [2][8][192]=3072 | sB1 3072 -> 7168
//      (epilogue exchange reuses sB0+sB1 region: 6144 floats = 3072 ull)
// OUT: sA [2][8][4]=64 | sB [2][8][512]=8192 | sL 4*512=2048 -> 10304
#define SMEM_FLOATS 10304
#define SMEM_BYTES  (SMEM_FLOATS * 4)

// ===== persistent device state =====
__device__ float g_h1a[Bdim * Hdim];
__device__ float g_h1b[Bdim * Hdim];
__device__ float g_h2a[Bdim * Hdim];
__device__ float g_h2b[Bdim * Hdim];
__device__ int   g_tok[Bdim];
__device__ unsigned g_key0[Tdim];
__device__ unsigned g_key1[Tdim];
__device__ unsigned g_bar_count;
__device__ volatile unsigned g_bar_gen;

// ===== packed f32x2 helpers =====
__device__ __forceinline__ void fma2(ull& d, ull a, ull b) {
    asm("fma.rn.f32x2 %0, %1, %2, %0;" : "+l"(d) : "l"(a), "l"(b));
}
__device__ __forceinline__ ull dup2(float b) {
    ull r; asm("mov.b64 %0, {%1, %1};" : "=l"(r) : "f"(b)); return r;
}
__device__ __forceinline__ float pick(ull v, int mm) {
    return __uint_as_float(mm ? (unsigned)(v >> 32) : (unsigned)(v & 0xffffffffull));
}

// ===== threefry2x32 =====
__device__ __forceinline__ void threefry2x32(unsigned k0, unsigned k1,
                                             unsigned c0, unsigned c1,
                                             unsigned& o0, unsigned& o1) {
    unsigned ks2 = k0 ^ k1 ^ 0x1BD11BDAu;
    unsigned x0 = c0 + k0;
    unsigned x1 = c1 + k1;
#define TF_RND(r) { x0 += x1; x1 = (x1 << (r)) | (x1 >> (32 - (r))); x1 ^= x0; }
    TF_RND(13) TF_RND(15) TF_RND(26) TF_RND(6)
    x0 += k1;  x1 += ks2 + 1u;
    TF_RND(17) TF_RND(29) TF_RND(16) TF_RND(24)
    x0 += ks2; x1 += k0 + 2u;
    TF_RND(13) TF_RND(15) TF_RND(26) TF_RND(6)
    x0 += k0;  x1 += k1 + 3u;
    TF_RND(17) TF_RND(29) TF_RND(16) TF_RND(24)
    x0 += k1;  x1 += ks2 + 4u;
    TF_RND(13) TF_RND(15) TF_RND(26) TF_RND(6)
    x0 += ks2; x1 += k0 + 5u;
#undef TF_RND
    o0 = x0; o1 = x1;
}

// ===== software grid barrier =====
__device__ __forceinline__ void grid_barrier() {
    __syncthreads();
    if (threadIdx.x == 0) {
        __threadfence();
        unsigned gen = g_bar_gen;
        if (atomicAdd(&g_bar_count, 1u) == NBLK - 1) {
            atomicExch(&g_bar_count, 0u);
            __threadfence();
            g_bar_gen = gen + 1u;
        } else {
            while (g_bar_gen == gen) __nanosleep(32);
        }
        __threadfence();
    }
    __syncthreads();
}

__device__ __forceinline__ void loadf8(float* r, const float* p) {
    float4 v0 = *reinterpret_cast<const float4*>(p);
    float4 v1 = *reinterpret_cast<const float4*>(p + 4);
    r[0] = v0.x; r[1] = v0.y; r[2] = v0.z; r[3] = v0.w;
    r[4] = v1.x; r[5] = v1.y; r[6] = v1.z; r[7] = v1.w;
}

// ===== fused GRU stage, warp-specialized =====
// Block tile: 32 m x 64 h (x3 gates, col = gate*64 + hl) for both gemms.
// Group 0 (tid 0-255):   gi = X @ Wih^T   (X = emb[tok] or h1)
// Group 1 (tid 256-511): gh = Hin @ Whh^T
// Each group: 8 warps = 4 mparts x 2 hparts; per thread 4 m-pairs x 3 gates = 12 acc.
// Epilogue: group1 ships acc via smem; group0 does gate combine + Hout write.
template<bool EMB>
__device__ void gru_stage(const float* __restrict__ X,
                          const float* __restrict__ Hin,
                          const float* __restrict__ Wih, const float* __restrict__ Whh,
                          const float* __restrict__ bih, const float* __restrict__ bhh,
                          float* __restrict__ Hout,
                          float* smem) {
    const int tid = threadIdx.x, bx = blockIdx.x;
    const int m0 = (bx >> 3) * 32;
    const int h0 = (bx & 7) * 64;
    const int grp = tid >> 8;
    const int gtid = tid & 255;
    float* sA = smem + (grp ? 512 : 0);            // [2][8][32]
    float* sB = smem + 1024 + (grp ? 3072 : 0);    // [2][8][192]

    const int warp = gtid >> 5, lane = gtid & 31;
    const int mpart = warp >> 1, hpart = warp & 1;
    const int hl = hpart * 32 + lane;
    const int h  = h0 + hl;

    // loader roles within each group
    const bool isB = (gtid < 192);
    bool isA = false;
    const float* gw = nullptr;
    const float* ga = nullptr;
    int arow = 0;
    if (isB) {
        int g = gtid >> 6, hl2 = gtid & 63;
        gw = (grp ? Whh : Wih) + (size_t)(g * Hdim + h0 + hl2) * Hdim;
    } else {
        int u = gtid - 192;
        if (u < 32) {
            isA = true; arow = u;
            if (grp)      ga = Hin + (size_t)(m0 + u) * Hdim;
            else if (EMB) ga = X + (size_t)g_tok[m0 + u] * Hdim;
            else          ga = X + (size_t)(m0 + u) * Hdim;
        }
    }

    ull acc[12];   // [mp*3 + g]
    #pragma unroll
    for (int i = 0; i < 12; i++) acc[i] = 0ull;

    float pw[8], pa[8];
    if (isB) loadf8(pw, gw);
    else if (isA) loadf8(pa, ga);
    if (isB) {
        #pragma unroll
        for (int k = 0; k < 8; k++) sB[k * 192 + gtid] = pw[k];
    } else if (isA) {
        #pragma unroll
        for (int k = 0; k < 8; k++) sA[k * 32 + arow] = pa[k];
    }
    __syncthreads();

    const int aoff = mpart * 8;

    #pragma unroll 1
    for (int k0 = 0; k0 < Hdim; k0 += 8) {
        const int buf = (k0 >> 3) & 1;
        const bool more = (k0 + 8) < Hdim;
        if (more) {
            if (isB) loadf8(pw, gw + k0 + 8);
            else if (isA) loadf8(pa, ga + k0 + 8);
        }
        #pragma unroll
        for (int k = 0; k < 8; k++) {
            const float* ap = sA + buf * 256 + k * 32 + aoff;
            ulonglong2 a01 = *reinterpret_cast<const ulonglong2*>(ap);
            ulonglong2 a23 = *reinterpret_cast<const ulonglong2*>(ap + 4);
            const float* bp = sB + buf * 1536 + k * 192 + hl;
            #pragma unroll
            for (int g = 0; g < 3; g++) {
                ull b = dup2(bp[g * 64]);
                fma2(acc[0 * 3 + g], a01.x, b);
                fma2(acc[1 * 3 + g], a01.y, b);
                fma2(acc[2 * 3 + g], a23.x, b);
                fma2(acc[3 * 3 + g], a23.y, b);
            }
        }
        if (more) {
            const int nb = buf ^ 1;
            if (isB) {
                #pragma unroll
                for (int k = 0; k < 8; k++) sB[nb * 1536 + k * 192 + gtid] = pw[k];
            } else if (isA) {
                #pragma unroll
                for (int k = 0; k < 8; k++) sA[nb * 256 + k * 32 + arow] = pa[k];
            }
        }
        __syncthreads();
    }

    // epilogue: group1 -> smem exchange, group0 combines
    ull* exch = reinterpret_cast<ull*>(smem + 1024);   // 3072 ull (reuses sB0+sB1)
    if (grp == 1) {
        #pragma unroll
        for (int i = 0; i < 12; i++) exch[gtid * 12 + i] = acc[i];
    }
    __syncthreads();
    if (grp == 0) {
        ull accH[12];
        #pragma unroll
        for (int i = 0; i < 12; i++) accH[i] = exch[gtid * 12 + i];
        const float bir  = bih[h];
        const float biz  = bih[Hdim + h];
        const float bin_ = bih[2 * Hdim + h];
        const float bhr  = bhh[h];
        const float bhz  = bhh[Hdim + h];
        const float bhn  = bhh[2 * Hdim + h];
        #pragma unroll
        for (int mp = 0; mp < 4; mp++) {
            #pragma unroll
            for (int mm = 0; mm < 2; mm++) {
                int m = m0 + mpart * 8 + mp * 2 + mm;
                float ir  = pick(acc[mp * 3 + 0], mm) + bir;
                float iz  = pick(acc[mp * 3 + 1], mm) + biz;
                float in_ = pick(acc[mp * 3 + 2], mm) + bin_;
                float hr  = pick(accH[mp * 3 + 0], mm) + bhr;
                float hz  = pick(accH[mp * 3 + 1], mm) + bhz;
                float hn  = pick(accH[mp * 3 + 2], mm) + bhn;
                float r = 1.f / (1.f + expf(-(ir + hr)));
                float z = 1.f / (1.f + expf(-(iz + hz)));
                float n = tanhf(in_ + r * hn);
                float hprev = Hin[(size_t)m * Hdim + h];
                Hout[(size_t)m * Hdim + h] = (1.f - z) * n + z * hprev;
            }
        }
    }
}

// ===== fused OUT + SAMPLE stage (512 threads, 1 class per thread) =====
__device__ void out_sample_stage(const float* __restrict__ H2, const float* __restrict__ Wout,
                                 const float* __restrict__ bout, float* __restrict__ out,
                                 float* __restrict__ tokout, int t, float* smem) {
    const int tid = threadIdx.x, bx = blockIdx.x;
    const int m0 = bx * 4;
    float* sA = smem;             // [2][8][4]
    float* sB = smem + 64;        // [2][8][512]
    float* sL = smem + 64 + 8192; // [4][512]

    const int warp = tid >> 5, lane = tid & 31;
    const int c = tid;            // class/col owned by this thread

    const float* gw = Wout + (size_t)c * Hdim;
    const float* ga = (tid < 4) ? H2 + (size_t)(m0 + tid) * Hdim : nullptr;

    ull acc[2];   // [mp] : rows (0,1), (2,3)
    acc[0] = acc[1] = 0ull;

    float pw[8], pa[8];
    loadf8(pw, gw);
    if (tid < 4) loadf8(pa, ga);
    #pragma unroll
    for (int k = 0; k < 8; k++) sB[k * 512 + c] = pw[k];
    if (tid < 4) {
        #pragma unroll
        for (int k = 0; k < 8; k++) sA[k * 4 + tid] = pa[k];
    }
    __syncthreads();

    #pragma unroll 1
    for (int k0 = 0; k0 < Hdim; k0 += 8) {
        const int buf = (k0 >> 3) & 1;
        const bool more = (k0 + 8) < Hdim;
        if (more) {
            loadf8(pw, gw + k0 + 8);
            if (tid < 4) loadf8(pa, ga + k0 + 8);
        }
        #pragma unroll
        for (int k = 0; k < 8; k++) {
            ulonglong2 aa = *reinterpret_cast<const ulonglong2*>(sA + buf * 32 + k * 4);
            ull b = dup2(sB[buf * 4096 + k * 512 + c]);
            fma2(acc[0], aa.x, b);
            fma2(acc[1], aa.y, b);
        }
        if (more) {
            const int nb = buf ^ 1;
            #pragma unroll
            for (int k = 0; k < 8; k++) sB[nb * 4096 + k * 512 + c] = pw[k];
            if (tid < 4) {
                #pragma unroll
                for (int k = 0; k < 8; k++) sA[nb * 32 + k * 4 + tid] = pa[k];
            }
        }
        __syncthreads();
    }

    const float bb = bout[c];
    #pragma unroll
    for (int mp = 0; mp < 2; mp++) {
        #pragma unroll
        for (int mm = 0; mm < 2; mm++) {
            int r = mp * 2 + mm;
            float v = pick(acc[mp], mm) + bb;
            sL[r * 512 + c] = v;
            out[(size_t)(m0 + r) * (Tdim * NCdim) + (size_t)t * NCdim + c] = v;
        }
    }
    __syncthreads();

    // ---- sampling: each thread owns one class of each of the 4 rows ----
    __shared__ float s_red[16];
    __shared__ float s_val[16];
    __shared__ int   s_idx[16];
    unsigned key0 = g_key0[t], key1 = g_key1[t];
    #pragma unroll 1
    for (int r = 0; r < 4; r++) {
        int b = m0 + r;
        float x = sL[r * 512 + c];

        // row max
        float mx = x;
        #pragma unroll
        for (int o = 16; o; o >>= 1) mx = fmaxf(mx, __shfl_xor_sync(0xffffffffu, mx, o));
        if (lane == 0) s_red[warp] = mx;
        __syncthreads();
        float m2 = s_red[0];
        #pragma unroll
        for (int k = 1; k < 16; k++) m2 = fmaxf(m2, s_red[k]);
        mx = m2;
        __syncthreads();

        // logsumexp
        float s = expf(x - mx);
        #pragma unroll
        for (int o = 16; o; o >>= 1) s += __shfl_xor_sync(0xffffffffu, s, o);
        if (lane == 0) s_red[warp] = s;
        __syncthreads();
        float s2 = 0.f;
        #pragma unroll
        for (int k = 0; k < 16; k++) s2 += s_red[k];
        float lse = logf(s2);
        __syncthreads();

        // gumbel + argmax (first-index tie break)
        const float tiny = 1.17549435e-38f;
        unsigned j = (unsigned)(b * NCdim + c);
        unsigned o0, o1;
        threefry2x32(key0, key1, 0u, j, o0, o1);
        unsigned bits = o0 ^ o1;
        float f = __uint_as_float((bits >> 9) | 0x3F800000u) - 1.0f;
        float u = fmaxf(tiny, f + tiny);
        float g = -logf(-logf(u));
        float best = ((x - mx) - lse) + g;
        int bi = c;
        #pragma unroll
        for (int o = 16; o; o >>= 1) {
            float ov = __shfl_xor_sync(0xffffffffu, best, o);
            int   oi = __shfl_xor_sync(0xffffffffu, bi, o);
            if (ov > best || (ov == best && oi < bi)) { best = ov; bi = oi; }
        }
        if (lane == 0) { s_val[warp] = best; s_idx[warp] = bi; }
        __syncthreads();
        if (tid == 0) {
            float bv = s_val[0]; int bidx = s_idx[0];
            #pragma unroll
            for (int k = 1; k < 16; k++) {
                if (s_val[k] > bv || (s_val[k] == bv && s_idx[k] < bidx)) {
                    bv = s_val[k]; bidx = s_idx[k];
                }
            }
            g_tok[b] = bidx;
            if (tokout) tokout[(size_t)b * Tdim + t] = (float)bidx;
        }
        __syncthreads();
    }
}

// ===== main persistent kernel =====
__global__ void __launch_bounds__(NTHR, 1)
prior_persistent(const float* __restrict__ note, const float* __restrict__ genre,
                 const float* __restrict__ Whid, const float* __restrict__ bhid,
                 const float* __restrict__ emb,
                 const float* __restrict__ Wih1, const float* __restrict__ Whh1,
                 const float* __restrict__ bih1, const float* __restrict__ bhh1,
                 const float* __restrict__ Wih2, const float* __restrict__ Whh2,
                 const float* __restrict__ bih2, const float* __restrict__ bhh2,
                 const float* __restrict__ Wout, const float* __restrict__ bout,
                 float* __restrict__ out, float* __restrict__ tokout) {
    extern __shared__ float smem[];
    const int tid = threadIdx.x, bx = blockIdx.x;

    // ---------- init ----------
    {
        int gidx = bx * NTHR + tid;
        if (gidx < Tdim) {
            unsigned o0, o1;
            threefry2x32(0u, 42u, 0u, (unsigned)gidx, o0, o1);
            g_key0[gidx] = o0; g_key1[gidx] = o1;
        }
        if (gidx < Bdim) g_tok[gidx] = 0;

        for (int r = 0; r < Bdim / NBLK; r++) {
            int b = bx * (Bdim / NBLK) + r;
            for (int i = tid; i < SKELdim; i += NTHR) smem[i] = note[b * SKELdim + i];
            for (int i = tid; i < GENdim; i += NTHR) smem[SKELdim + i] = genre[b * GENdim + i];
            __syncthreads();
            for (int j = tid; j < Hdim; j += NTHR) {
                const float* w = Whid + (size_t)j * (SKELdim + GENdim);
                float acc = 0.f;
                #pragma unroll 8
                for (int k = 0; k < SKELdim + GENdim; k++) acc = fmaf(smem[k], w[k], acc);
                g_h1a[(size_t)b * Hdim + j] = acc + bhid[j];
            }
            __syncthreads();
        }
    }
    grid_barrier();

    for (int t = 0; t < Tdim; t++) {
        const float* h1r; float* h1w; const float* h2r; float* h2w;
        if (t & 1) { h1r = g_h1b; h1w = g_h1a; h2r = g_h2b; h2w = g_h2a; }
        else       { h1r = g_h1a; h1w = g_h1b; h2r = g_h2a; h2w = g_h2b; }

        gru_stage<true>(emb, h1r, Wih1, Whh1, bih1, bhh1, h1w, smem);
        grid_barrier();

        const float* hp2 = (t == 0) ? (const float*)h1w : h2r;
        gru_stage<false>(h1w, hp2, Wih2, Whh2, bih2, bhh2, h2w, smem);
        grid_barrier();

        out_sample_stage(h2w, Wout, bout, out, tokout, t, smem);
        grid_barrier();
    }
}

// ===== launch: ONE graph node =====
extern "C" void kernel_launch(void* const* d_in, const int* in_sizes, int n_in,
                              void* d_out, int out_size) {
    const float* note  = (const float*)d_in[1];
    const float* genre = (const float*)d_in[2];
    const float* W_hid = (const float*)d_in[3];
    const float* b_hid = (const float*)d_in[4];
    const float* emb   = (const float*)d_in[5];
    const float* W_ih1 = (const float*)d_in[6];
    const float* W_hh1 = (const float*)d_in[7];
    const float* b_ih1 = (const float*)d_in[8];
    const float* b_hh1 = (const float*)d_in[9];
    const float* W_ih2 = (const float*)d_in[10];
    const float* W_hh2 = (const float*)d_in[11];
    const float* b_ih2 = (const float*)d_in[12];
    const float* b_hh2 = (const float*)d_in[13];
    const float* W_out = (const float*)d_in[14];
    const float* b_out = (const float*)d_in[15];

    float* out = (float*)d_out;
    const long long need = (long long)Bdim * Tdim * NCdim + (long long)Bdim * Tdim;
    float* tokout = ((long long)out_size >= need) ? (out + (size_t)Bdim * Tdim * NCdim) : nullptr;

    cudaFuncSetAttribute(prior_persistent,
                         cudaFuncAttributeMaxDynamicSharedMemorySize, SMEM_BYTES);

    prior_persistent<<<NBLK, NTHR, SMEM_BYTES>>>(note, genre, W_hid, b_hid, emb,
                                                 W_ih1, W_hh1, b_ih1, b_hh1,
                                                 W_ih2, W_hh2, b_ih2, b_hh2,
                                                 W_out, b_out, out, tokout);
}

// round 10
// speedup vs baseline: 1.0523x; 1.0523x over previous
#include <cuda_runtime.h>
#include <cuda_bf16.h>
#include <stdint.h>
#include <math.h>

// ===== problem dims =====
#define Bdim 512
#define Tdim 256
#define Hdim 512
#define NCdim 512
#define SKELdim 256
#define GENdim 16

#define NBLK 128
#define NTHR 256

#define LSTRIDE 6144   // bytes per (ntile,vc) B chunk, layer (192n x 16k x bf16)
#define OSTRIDE 4096   // bytes per (ntile,vc) B chunk, out   (128n x 16k x bf16)

// ===== persistent device state =====
__device__ float g_h1[Bdim * Hdim];
__device__ float g_h2[Bdim * Hdim];
__device__ float g_gi[Bdim * 3 * Hdim];
__device__ float g_gh[Bdim * 3 * Hdim];
__device__ int   g_tok[Bdim];
__device__ unsigned g_key0[Tdim];
__device__ unsigned g_key1[Tdim];
__device__ unsigned g_bar_count;
__device__ volatile unsigned g_bar_gen;

// bf16 split activations [3][512][512]
__device__ __align__(16) __nv_bfloat16 g_embsplit[3 * 512 * 512];
__device__ __align__(16) __nv_bfloat16 g_h1split[3 * 512 * 512];
__device__ __align__(16) __nv_bfloat16 g_h2split[3 * 512 * 512];

// pre-split virtual-K weight blobs
__device__ __align__(16) unsigned char g_blob_ih1[8 * 192 * (size_t)LSTRIDE];
__device__ __align__(16) unsigned char g_blob_hh1[8 * 192 * (size_t)LSTRIDE];
__device__ __align__(16) unsigned char g_blob_ih2[8 * 192 * (size_t)LSTRIDE];
__device__ __align__(16) unsigned char g_blob_hh2[8 * 192 * (size_t)LSTRIDE];
__device__ __align__(16) unsigned char g_blob_out[4 * 192 * (size_t)OSTRIDE];

// ===== helpers =====
__device__ __forceinline__ uint32_t smem_u32(const void* p) {
    uint32_t a;
    asm("{ .reg .u64 tmp; cvta.to.shared.u64 tmp, %1; cvt.u32.u64 %0, tmp; }" : "=r"(a) : "l"(p));
    return a;
}
__device__ __forceinline__ void ldsm4(uint32_t* r, uint32_t addr) {
    asm volatile("ldmatrix.sync.aligned.m8n8.x4.shared.b16 {%0,%1,%2,%3}, [%4];"
                 : "=r"(r[0]), "=r"(r[1]), "=r"(r[2]), "=r"(r[3]) : "r"(addr));
}
__device__ __forceinline__ void mma_bf16(float* c, const uint32_t* a, const uint32_t* b) {
    asm volatile("mma.sync.aligned.m16n8k16.row.col.f32.bf16.bf16.f32 "
                 "{%0,%1,%2,%3}, {%4,%5,%6,%7}, {%8,%9}, {%0,%1,%2,%3};"
                 : "+f"(c[0]), "+f"(c[1]), "+f"(c[2]), "+f"(c[3])
                 : "r"(a[0]), "r"(a[1]), "r"(a[2]), "r"(a[3]), "r"(b[0]), "r"(b[1]));
}
__device__ __forceinline__ void split3(float x, __nv_bfloat16& b0, __nv_bfloat16& b1, __nv_bfloat16& b2) {
    b0 = __float2bfloat16_rn(x);
    float r1 = x - __bfloat162float(b0);
    b1 = __float2bfloat16_rn(r1);
    b2 = __float2bfloat16_rn(r1 - __bfloat162float(b1));
}
// product p -> (A split, B split): (0,0),(0,1),(1,0),(1,1),(0,2),(2,0)
__device__ __forceinline__ int PA_of(int p) { return (p == 2 || p == 3) ? 1 : (p == 5 ? 2 : 0); }

// ===== threefry2x32 =====
__device__ __forceinline__ void threefry2x32(unsigned k0, unsigned k1,
                                             unsigned c0, unsigned c1,
                                             unsigned& o0, unsigned& o1) {
    unsigned ks2 = k0 ^ k1 ^ 0x1BD11BDAu;
    unsigned x0 = c0 + k0;
    unsigned x1 = c1 + k1;
#define TF_RND(r) { x0 += x1; x1 = (x1 << (r)) | (x1 >> (32 - (r))); x1 ^= x0; }
    TF_RND(13) TF_RND(15) TF_RND(26) TF_RND(6)
    x0 += k1;  x1 += ks2 + 1u;
    TF_RND(17) TF_RND(29) TF_RND(16) TF_RND(24)
    x0 += ks2; x1 += k0 + 2u;
    TF_RND(13) TF_RND(15) TF_RND(26) TF_RND(6)
    x0 += k0;  x1 += k1 + 3u;
    TF_RND(17) TF_RND(29) TF_RND(16) TF_RND(24)
    x0 += k1;  x1 += ks2 + 4u;
    TF_RND(13) TF_RND(15) TF_RND(26) TF_RND(6)
    x0 += ks2; x1 += k0 + 5u;
#undef TF_RND
    o0 = x0; o1 = x1;
}

// ===== software grid barrier =====
__device__ __forceinline__ void grid_barrier() {
    __syncthreads();
    if (threadIdx.x == 0) {
        __threadfence();
        unsigned gen = g_bar_gen;
        if (atomicAdd(&g_bar_count, 1u) == NBLK - 1) {
            atomicExch(&g_bar_count, 0u);
            __threadfence();
            g_bar_gen = gen + 1u;
        } else {
            while (g_bar_gen == gen) __nanosleep(32);
        }
        __threadfence();
    }
    __syncthreads();
}

// ===== weight blob packing (init) =====
__device__ void pack_blob(const float* __restrict__ W, int N, int TW,
                          unsigned char* __restrict__ blob, int gt, int gN) {
    const int PBv[6] = {0, 1, 0, 1, 2, 0};
    int units = N * 32;
    for (int u = gt; u < units; u += gN) {
        int n = u >> 5, kc = u & 31;
        const float* wp = W + (size_t)n * 512 + kc * 16;
        __align__(16) __nv_bfloat16 sp[3][16];
        #pragma unroll
        for (int i = 0; i < 16; i++) split3(wp[i], sp[0][i], sp[1][i], sp[2][i]);
        int ntile = n / TW, nl = n % TW;
        #pragma unroll
        for (int p = 0; p < 6; p++) {
            int vc = p * 32 + kc;
            unsigned char* d = blob + ((size_t)(ntile * 192 + vc) * TW + nl) * 32;
            const uint4* s4 = reinterpret_cast<const uint4*>(sp[PBv[p]]);
            *reinterpret_cast<uint4*>(d)      = s4[0];
            *reinterpret_cast<uint4*>(d + 16) = s4[1];
        }
    }
}

// ===== layer GEMM: C[64m x 192n] raw (no bias), virtual K = 3072 =====
__device__ void gemm_layer(const __nv_bfloat16* __restrict__ Abase, bool useEmb,
                           const unsigned char* __restrict__ blob,
                           float* __restrict__ Cdst,
                           int mt, int nt, char* sm) {
    const int tid = threadIdx.x;
    const int warp = tid >> 5, lane = tid & 31;
    const int mpart = warp >> 2, npart = warp & 3;
    const int m0 = mt * 64, n0 = nt * 192;

    __nv_bfloat16* sA = (__nv_bfloat16*)sm;            // [2][64][16]
    __nv_bfloat16* sB = (__nv_bfloat16*)(sm + 4096);   // [2][192][16]
    const __nv_bfloat16** sRow = (const __nv_bfloat16**)(sm + 16384);

    if (tid < 64) {
        int m = m0 + tid;
        sRow[tid] = useEmb ? Abase + (size_t)g_tok[m] * 512 : Abase + (size_t)m * 512;
    }
    __syncthreads();

    const bool isA = (tid < 128);
    const int aR = tid >> 1, aH = tid & 1;
    const int w0 = tid - 128;       // B unit for unit0 (if !isA)
    const int w1 = tid + 128;       // B unit for unit1 (always)
    const unsigned char* bBase = blob + (size_t)nt * 192 * LSTRIDE;
    const __nv_bfloat16* aRowP = sRow[aR & 63];

    float acc[2][6][4];
    #pragma unroll
    for (int i = 0; i < 2; i++)
        #pragma unroll
        for (int j = 0; j < 6; j++)
            #pragma unroll
            for (int q = 0; q < 4; q++) acc[i][j][q] = 0.f;

    uint32_t sAu = smem_u32(sA), sBu = smem_u32(sB);

    uint4 pf0, pf1;
    {   // prologue: chunk 0 (p=0 -> split 0, kc=0)
        if (isA) pf0 = *reinterpret_cast<const uint4*>(aRowP + aH * 8);
        else     pf0 = *reinterpret_cast<const uint4*>(bBase + (size_t)w0 * 16);
        pf1 = *reinterpret_cast<const uint4*>(bBase + (size_t)w1 * 16);
    }

    const int arow = mpart * 32 + (lane & 15);
    const int ahalf = lane >> 4;
    const int g = lane >> 3;
    const int brow0 = npart * 48 + (lane & 7) + ((g >> 1) * 8);
    const int bhalf = g & 1;

    #pragma unroll 2
    for (int vc = 0; vc < 192; vc++) {
        const int buf = vc & 1;
        // store current prefetch
        if (isA) *reinterpret_cast<uint4*>(sA + buf * 1024 + tid * 8) = pf0;
        else     *reinterpret_cast<uint4*>(sB + buf * 3072 + w0 * 8) = pf0;
        *reinterpret_cast<uint4*>(sB + buf * 3072 + w1 * 8) = pf1;
        __syncthreads();

        // prefetch next chunk
        if (vc + 1 < 192) {
            int vn = vc + 1;
            if (isA) {
                int p = vn >> 5, kc = vn & 31;
                int s = PA_of(p);
                pf0 = *reinterpret_cast<const uint4*>(aRowP + s * 262144 + kc * 16 + aH * 8);
            } else {
                pf0 = *reinterpret_cast<const uint4*>(bBase + (size_t)vn * LSTRIDE + (size_t)w0 * 16);
            }
            pf1 = *reinterpret_cast<const uint4*>(bBase + (size_t)vn * LSTRIDE + (size_t)w1 * 16);
        }

        // compute
        uint32_t aF[2][4], bF[3][4];
        #pragma unroll
        for (int mt2 = 0; mt2 < 2; mt2++) {
            uint32_t ad = sAu + (buf * 1024 + (arow + mt2 * 16) * 16 + ahalf * 8) * 2;
            ldsm4(aF[mt2], ad);
        }
        #pragma unroll
        for (int bt = 0; bt < 3; bt++) {
            uint32_t bd = sBu + (buf * 3072 + (brow0 + bt * 16) * 16 + bhalf * 8) * 2;
            ldsm4(bF[bt], bd);
        }
        #pragma unroll
        for (int mt2 = 0; mt2 < 2; mt2++)
            #pragma unroll
            for (int j = 0; j < 3; j++) {
                mma_bf16(acc[mt2][j * 2 + 0], aF[mt2], &bF[j][0]);
                mma_bf16(acc[mt2][j * 2 + 1], aF[mt2], &bF[j][2]);
            }
        __syncthreads();
    }

    // epilogue: raw C -> Cdst [m][1536]
    #pragma unroll
    for (int mt2 = 0; mt2 < 2; mt2++) {
        int row = m0 + mpart * 32 + mt2 * 16 + (lane >> 2);
        #pragma unroll
        for (int nt6 = 0; nt6 < 6; nt6++) {
            int col = n0 + npart * 48 + nt6 * 8 + (lane & 3) * 2;
            float* c = acc[mt2][nt6];
            *reinterpret_cast<float2*>(Cdst + (size_t)row * 1536 + col) = make_float2(c[0], c[1]);
            *reinterpret_cast<float2*>(Cdst + (size_t)(row + 8) * 1536 + col) = make_float2(c[2], c[3]);
        }
    }
}

// ===== out GEMM: logits[32m x 128n] = h2 @ Wout^T + bout -> out[:, t, :] =====
__device__ void gemm_out(const __nv_bfloat16* __restrict__ Abase,
                         const unsigned char* __restrict__ blob,
                         const float* __restrict__ bout,
                         float* __restrict__ out, int t,
                         int mt, int nt, char* sm) {
    const int tid = threadIdx.x;
    const int warp = tid >> 5, lane = tid & 31;
    const int mpart = warp >> 2, npart = warp & 3;
    const int m0 = mt * 32, n0 = nt * 128;

    __nv_bfloat16* sA = (__nv_bfloat16*)sm;            // [2][32][16]
    __nv_bfloat16* sB = (__nv_bfloat16*)(sm + 4096);   // [2][128][16]
    const __nv_bfloat16** sRow = (const __nv_bfloat16**)(sm + 16384);

    if (tid < 32) sRow[tid] = Abase + (size_t)(m0 + tid) * 512;
    __syncthreads();

    const bool isA = (tid < 64);
    const int aH = tid & 1;
    const int w0 = tid - 64;        // B unit for unit0 (if !isA): 0..191
    const int w1 = tid + 192;       // B unit for unit1 (valid if tid<64): 192..255
    const unsigned char* bBase = blob + (size_t)nt * 192 * OSTRIDE;
    const __nv_bfloat16* aRowP = sRow[(tid >> 1) & 31];

    float acc[4][4];
    #pragma unroll
    for (int j = 0; j < 4; j++)
        #pragma unroll
        for (int q = 0; q < 4; q++) acc[j][q] = 0.f;

    uint32_t sAu = smem_u32(sA), sBu = smem_u32(sB);

    uint4 pf0, pf1;
    if (isA) {
        pf0 = *reinterpret_cast<const uint4*>(aRowP + aH * 8);
        pf1 = *reinterpret_cast<const uint4*>(bBase + (size_t)w1 * 16);
    } else {
        pf0 = *reinterpret_cast<const uint4*>(bBase + (size_t)w0 * 16);
    }

    const int arow = mpart * 16 + (lane & 15);
    const int ahalf = lane >> 4;
    const int g = lane >> 3;
    const int brow0 = npart * 32 + (lane & 7) + ((g >> 1) * 8);
    const int bhalf = g & 1;

    #pragma unroll 2
    for (int vc = 0; vc < 192; vc++) {
        const int buf = vc & 1;
        if (isA) {
            *reinterpret_cast<uint4*>(sA + buf * 512 + tid * 8) = pf0;
            *reinterpret_cast<uint4*>(sB + buf * 2048 + w1 * 8) = pf1;
        } else {
            *reinterpret_cast<uint4*>(sB + buf * 2048 + w0 * 8) = pf0;
        }
        __syncthreads();

        if (vc + 1 < 192) {
            int vn = vc + 1;
            if (isA) {
                int p = vn >> 5, kc = vn & 31;
                int s = PA_of(p);
                pf0 = *reinterpret_cast<const uint4*>(aRowP + s * 262144 + kc * 16 + aH * 8);
                pf1 = *reinterpret_cast<const uint4*>(bBase + (size_t)vn * OSTRIDE + (size_t)w1 * 16);
            } else {
                pf0 = *reinterpret_cast<const uint4*>(bBase + (size_t)vn * OSTRIDE + (size_t)w0 * 16);
            }
        }

        uint32_t aF[4], bF[2][4];
        {
            uint32_t ad = sAu + (buf * 512 + arow * 16 + ahalf * 8) * 2;
            ldsm4(aF, ad);
        }
        #pragma unroll
        for (int bt = 0; bt < 2; bt++) {
            uint32_t bd = sBu + (buf * 2048 + (brow0 + bt * 16) * 16 + bhalf * 8) * 2;
            ldsm4(bF[bt], bd);
        }
        #pragma unroll
        for (int j = 0; j < 2; j++) {
            mma_bf16(acc[j * 2 + 0], aF, &bF[j][0]);
            mma_bf16(acc[j * 2 + 1], aF, &bF[j][2]);
        }
        __syncthreads();
    }

    int row = m0 + mpart * 16 + (lane >> 2);
    #pragma unroll
    for (int nt4 = 0; nt4 < 4; nt4++) {
        int col = n0 + npart * 32 + nt4 * 8 + (lane & 3) * 2;
        float b0 = bout[col], b1 = bout[col + 1];
        float* c = acc[nt4];
        float* o0 = out + (size_t)row * (Tdim * NCdim) + (size_t)t * NCdim + col;
        float* o1 = out + (size_t)(row + 8) * (Tdim * NCdim) + (size_t)t * NCdim + col;
        *reinterpret_cast<float2*>(o0) = make_float2(c[0] + b0, c[1] + b1);
        *reinterpret_cast<float2*>(o1) = make_float2(c[2] + b0, c[3] + b1);
    }
}

// ===== GRU combine (verified math) + split writes, in-place =====
__device__ void combine_stage(const float* __restrict__ bih, const float* __restrict__ bhh,
                              const float* __restrict__ Hprev, float* __restrict__ Hout,
                              __nv_bfloat16* __restrict__ Hsplit) {
    const int tid = threadIdx.x, bx = blockIdx.x;
    int base = bx * (Bdim * Hdim / NBLK);
    #pragma unroll 1
    for (int j = 0; j < (Bdim * Hdim / NBLK) / NTHR; j++) {
        int idx = base + j * NTHR + tid;
        int b = idx >> 9, h = idx & (Hdim - 1);
        const float* gib = g_gi + (size_t)b * (3 * Hdim);
        const float* ghb = g_gh + (size_t)b * (3 * Hdim);
        float ir = gib[h] + bih[h];
        float iz = gib[Hdim + h] + bih[Hdim + h];
        float in_ = gib[2 * Hdim + h] + bih[2 * Hdim + h];
        float hr = ghb[h] + bhh[h];
        float hz = ghb[Hdim + h] + bhh[Hdim + h];
        float hn = ghb[2 * Hdim + h] + bhh[2 * Hdim + h];
        float r = 1.f / (1.f + expf(-(ir + hr)));
        float z = 1.f / (1.f + expf(-(iz + hz)));
        float n = tanhf(in_ + r * hn);
        float hout = (1.f - z) * n + z * Hprev[idx];
        Hout[idx] = hout;
        __nv_bfloat16 s0, s1, s2;
        split3(hout, s0, s1, s2);
        Hsplit[idx] = s0;
        Hsplit[262144 + idx] = s1;
        Hsplit[2 * 262144 + idx] = s2;
    }
}

// ===== sample stage (verified R3 logic): 4 rows per block =====
__device__ void sample_stage(const float* __restrict__ out, float* __restrict__ tokout, int t) {
    __shared__ float s_red[8];
    __shared__ float s_val[8];
    __shared__ int   s_idx[8];
    const int tid = threadIdx.x, bx = blockIdx.x;
    const int lane = tid & 31, wrp = tid >> 5;
    unsigned key0 = g_key0[t], key1 = g_key1[t];
    #pragma unroll 1
    for (int i = 0; i < Bdim / NBLK; i++) {
        int b = bx + i * NBLK;
        const float* row = out + (size_t)b * Tdim * NCdim + (size_t)t * NCdim;

        float mx = -3.402823466e38f;
        for (int c = tid; c < NCdim; c += NTHR) mx = fmaxf(mx, row[c]);
        #pragma unroll
        for (int o = 16; o; o >>= 1) mx = fmaxf(mx, __shfl_xor_sync(0xffffffffu, mx, o));
        if (lane == 0) s_red[wrp] = mx;
        __syncthreads();
        float m2 = s_red[0];
        #pragma unroll
        for (int k = 1; k < 8; k++) m2 = fmaxf(m2, s_red[k]);
        mx = m2;
        __syncthreads();

        float s = 0.f;
        for (int c = tid; c < NCdim; c += NTHR) s += expf(row[c] - mx);
        #pragma unroll
        for (int o = 16; o; o >>= 1) s += __shfl_xor_sync(0xffffffffu, s, o);
        if (lane == 0) s_red[wrp] = s;
        __syncthreads();
        float s2 = 0.f;
        #pragma unroll
        for (int k = 0; k < 8; k++) s2 += s_red[k];
        float lse = logf(s2);
        __syncthreads();

        float best = -3.402823466e38f;
        int bi = NCdim;
        const float tiny = 1.17549435e-38f;
        for (int c = tid; c < NCdim; c += NTHR) {
            unsigned j = (unsigned)(b * NCdim + c);
            unsigned o0, o1;
            threefry2x32(key0, key1, 0u, j, o0, o1);
            unsigned bits = o0 ^ o1;
            float f = __uint_as_float((bits >> 9) | 0x3F800000u) - 1.0f;
            float u = fmaxf(tiny, f + tiny);
            float g = -logf(-logf(u));
            float v = ((row[c] - mx) - lse) + g;
            if (v > best) { best = v; bi = c; }
        }
        #pragma unroll
        for (int o = 16; o; o >>= 1) {
            float ov = __shfl_xor_sync(0xffffffffu, best, o);
            int   oi = __shfl_xor_sync(0xffffffffu, bi, o);
            if (ov > best || (ov == best && oi < bi)) { best = ov; bi = oi; }
        }
        if (lane == 0) { s_val[wrp] = best; s_idx[wrp] = bi; }
        __syncthreads();
        if (tid == 0) {
            float bv = s_val[0]; int bidx = s_idx[0];
            #pragma unroll
            for (int k = 1; k < 8; k++) {
                if (s_val[k] > bv || (s_val[k] == bv && s_idx[k] < bidx)) { bv = s_val[k]; bidx = s_idx[k]; }
            }
            g_tok[b] = bidx;
            if (tokout) tokout[(size_t)b * Tdim + t] = (float)bidx;
        }
        __syncthreads();
    }
}

// ===== main persistent kernel =====
__global__ void __launch_bounds__(NTHR, 1)
prior_mma(const float* __restrict__ note, const float* __restrict__ genre,
          const float* __restrict__ Whid, const float* __restrict__ bhid,
          const float* __restrict__ emb,
          const float* __restrict__ Wih1, const float* __restrict__ Whh1,
          const float* __restrict__ bih1, const float* __restrict__ bhh1,
          const float* __restrict__ Wih2, const float* __restrict__ Whh2,
          const float* __restrict__ bih2, const float* __restrict__ bhh2,
          const float* __restrict__ Wout, const float* __restrict__ bout,
          float* __restrict__ out, float* __restrict__ tokout) {
    __shared__ __align__(16) char sm[16896];
    const int tid = threadIdx.x, bx = blockIdx.x;

    // ---------- init ----------
    {
        int gt = bx * NTHR + tid, gN = NBLK * NTHR;
        if (gt < Tdim) {
            unsigned o0, o1;
            threefry2x32(0u, 42u, 0u, (unsigned)gt, o0, o1);
            g_key0[gt] = o0; g_key1[gt] = o1;
        }
        if (gt < Bdim) g_tok[gt] = 0;

        pack_blob(Wih1, 1536, 192, g_blob_ih1, gt, gN);
        pack_blob(Whh1, 1536, 192, g_blob_hh1, gt, gN);
        pack_blob(Wih2, 1536, 192, g_blob_ih2, gt, gN);
        pack_blob(Whh2, 1536, 192, g_blob_hh2, gt, gN);
        pack_blob(Wout, 512, 128, g_blob_out, gt, gN);

        // emb split table
        for (int idx = gt; idx < 512 * 512; idx += gN) {
            __nv_bfloat16 s0, s1, s2;
            split3(emb[idx], s0, s1, s2);
            g_embsplit[idx] = s0;
            g_embsplit[262144 + idx] = s1;
            g_embsplit[2 * 262144 + idx] = s2;
        }

        // h1 init = concat(note, genre) @ Whid^T + bhid (+ splits)
        float* sInit = (float*)sm;
        for (int r = 0; r < Bdim / NBLK; r++) {
            int b = bx * (Bdim / NBLK) + r;
            for (int i = tid; i < SKELdim; i += NTHR) sInit[i] = note[b * SKELdim + i];
            for (int i = tid; i < GENdim; i += NTHR) sInit[SKELdim + i] = genre[b * GENdim + i];
            __syncthreads();
            for (int j = tid; j < Hdim; j += NTHR) {
                const float* w = Whid + (size_t)j * (SKELdim + GENdim);
                float acc = 0.f;
                #pragma unroll 8
                for (int k = 0; k < SKELdim + GENdim; k++) acc = fmaf(sInit[k], w[k], acc);
                acc += bhid[j];
                int idx = b * Hdim + j;
                g_h1[idx] = acc;
                __nv_bfloat16 s0, s1, s2;
                split3(acc, s0, s1, s2);
                g_h1split[idx] = s0;
                g_h1split[262144 + idx] = s1;
                g_h1split[2 * 262144 + idx] = s2;
            }
            __syncthreads();
        }
    }
    grid_barrier();

    const bool isGh = (bx >= 64);
    const int rj = bx & 63;
    const int mt = rj >> 3, nt = rj & 7;

    for (int t = 0; t < Tdim; t++) {
        // ---- layer 1: gi = emb[tok] @ Wih1^T ; gh = h1 @ Whh1^T ----
        gemm_layer(isGh ? g_h1split : g_embsplit, !isGh,
                   isGh ? g_blob_hh1 : g_blob_ih1,
                   isGh ? g_gh : g_gi, mt, nt, sm);
        grid_barrier();
        combine_stage(bih1, bhh1, g_h1, g_h1, g_h1split);
        grid_barrier();

        // ---- layer 2: gi = h1 @ Wih2^T ; gh = h2prev @ Whh2^T ----
        const __nv_bfloat16* a2 = isGh ? ((t == 0) ? g_h1split : g_h2split) : g_h1split;
        gemm_layer(a2, false,
                   isGh ? g_blob_hh2 : g_blob_ih2,
                   isGh ? g_gh : g_gi, mt, nt, sm);
        grid_barrier();
        combine_stage(bih2, bhh2, (t == 0) ? g_h1 : g_h2, g_h2, g_h2split);
        grid_barrier();

        // ---- out GEMM (64 CTAs) ----
        if (bx < 64) gemm_out(g_h2split, g_blob_out, bout, out, t, bx >> 2, bx & 3, sm);
        grid_barrier();

        sample_stage(out, tokout, t);
        grid_barrier();
    }
}

// ===== launch: ONE graph node =====
extern "C" void kernel_launch(void* const* d_in, const int* in_sizes, int n_in,
                              void* d_out, int out_size) {
    const float* note  = (const float*)d_in[1];
    const float* genre = (const float*)d_in[2];
    const float* W_hid = (const float*)d_in[3];
    const float* b_hid = (const float*)d_in[4];
    const float* emb   = (const float*)d_in[5];
    const float* W_ih1 = (const float*)d_in[6];
    const float* W_hh1 = (const float*)d_in[7];
    const float* b_ih1 = (const float*)d_in[8];
    const float* b_hh1 = (const float*)d_in[9];
    const float* W_ih2 = (const float*)d_in[10];
    const float* W_hh2 = (const float*)d_in[11];
    const float* b_ih2 = (const float*)d_in[12];
    const float* b_hh2 = (const float*)d_in[13];
    const float* W_out = (const float*)d_in[14];
    const float* b_out = (const float*)d_in[15];

    float* out = (float*)d_out;
    const long long need = (long long)Bdim * Tdim * NCdim + (long long)Bdim * Tdim;
    float* tokout = ((long long)out_size >= need) ? (out + (size_t)Bdim * Tdim * NCdim) : nullptr;

    prior_mma<<<NBLK, NTHR>>>(note, genre, W_hid, b_hid, emb,
                              W_ih1, W_hh1, b_ih1, b_hh1,
                              W_ih2, W_hh2, b_ih2, b_hh2,
                              W_out, b_out, out, tokout);
}

// round 11
// speedup vs baseline: 1.5885x; 1.5096x over previous
#include <cuda_runtime.h>
#include <cuda_bf16.h>
#include <stdint.h>
#include <math.h>

// ===== problem dims =====
#define Bdim 512
#define Tdim 256
#define Hdim 512
#define NCdim 512
#define SKELdim 256
#define GENdim 16

#define NBLK 128
#define NTHR 512

#define LSTRIDE 6144   // bytes per (ntile,vc) B chunk, layer (192n x 16k bf16)
#define OSTRIDE 2048   // bytes per (ntile,vc) B chunk, out   (64n x 16k bf16)

// ===== persistent device state =====
__device__ float g_h1[Bdim * Hdim];
__device__ float g_h2[Bdim * Hdim];
__device__ float g_gi[Bdim * 3 * Hdim];
__device__ float g_gh[Bdim * 3 * Hdim];
__device__ int   g_tok[Bdim];
__device__ unsigned g_key0[Tdim];
__device__ unsigned g_key1[Tdim];
__device__ unsigned g_bar_count;
__device__ volatile unsigned g_bar_gen;

// bf16 split activations [3][512][512]
__device__ __align__(16) __nv_bfloat16 g_embsplit[3 * 512 * 512];
__device__ __align__(16) __nv_bfloat16 g_h1split[3 * 512 * 512];
__device__ __align__(16) __nv_bfloat16 g_h2split[3 * 512 * 512];

// pre-split virtual-K weight blobs
__device__ __align__(16) unsigned char g_blob_ih1[8 * 192 * (size_t)LSTRIDE];
__device__ __align__(16) unsigned char g_blob_hh1[8 * 192 * (size_t)LSTRIDE];
__device__ __align__(16) unsigned char g_blob_ih2[8 * 192 * (size_t)LSTRIDE];
__device__ __align__(16) unsigned char g_blob_hh2[8 * 192 * (size_t)LSTRIDE];
__device__ __align__(16) unsigned char g_blob_out[8 * 192 * (size_t)OSTRIDE];

// ===== shared memory layout =====
struct __align__(16) SMem {
    __nv_bfloat16 A[2 * 2048];   // layer: [2][64 rows][32k swizzled]; out: [2][32][32]
    __nv_bfloat16 B[2 * 6144];   // layer: [2][192][32]; out: [2][64][32]
    float red[16];
    float val[16];
    int   idx[16];
    float init[SKELdim + GENdim];
};

// ===== helpers =====
__device__ __forceinline__ uint32_t smem_u32(const void* p) {
    uint32_t a;
    asm("{ .reg .u64 tmp; cvta.to.shared.u64 tmp, %1; cvt.u32.u64 %0, tmp; }" : "=r"(a) : "l"(p));
    return a;
}
__device__ __forceinline__ void ldsm4(uint32_t* r, uint32_t addr) {
    asm volatile("ldmatrix.sync.aligned.m8n8.x4.shared.b16 {%0,%1,%2,%3}, [%4];"
                 : "=r"(r[0]), "=r"(r[1]), "=r"(r[2]), "=r"(r[3]) : "r"(addr));
}
__device__ __forceinline__ void ldsm2(uint32_t* r, uint32_t addr) {
    asm volatile("ldmatrix.sync.aligned.m8n8.x2.shared.b16 {%0,%1}, [%2];"
                 : "=r"(r[0]), "=r"(r[1]) : "r"(addr));
}
__device__ __forceinline__ void mma_bf16(float* c, const uint32_t* a, const uint32_t* b) {
    asm volatile("mma.sync.aligned.m16n8k16.row.col.f32.bf16.bf16.f32 "
                 "{%0,%1,%2,%3}, {%4,%5,%6,%7}, {%8,%9}, {%0,%1,%2,%3};"
                 : "+f"(c[0]), "+f"(c[1]), "+f"(c[2]), "+f"(c[3])
                 : "r"(a[0]), "r"(a[1]), "r"(a[2]), "r"(a[3]), "r"(b[0]), "r"(b[1]));
}
__device__ __forceinline__ void split3(float x, __nv_bfloat16& b0, __nv_bfloat16& b1, __nv_bfloat16& b2) {
    b0 = __float2bfloat16_rn(x);
    float r1 = x - __bfloat162float(b0);
    b1 = __float2bfloat16_rn(r1);
    b2 = __float2bfloat16_rn(r1 - __bfloat162float(b1));
}
// product p -> (A split, B split): (0,0),(0,1),(1,0),(1,1),(0,2),(2,0)
__device__ __forceinline__ int PA_of(int p) { return (p == 2 || p == 3) ? 1 : (p == 5 ? 2 : 0); }

// ===== threefry2x32 =====
__device__ __forceinline__ void threefry2x32(unsigned k0, unsigned k1,
                                             unsigned c0, unsigned c1,
                                             unsigned& o0, unsigned& o1) {
    unsigned ks2 = k0 ^ k1 ^ 0x1BD11BDAu;
    unsigned x0 = c0 + k0;
    unsigned x1 = c1 + k1;
#define TF_RND(r) { x0 += x1; x1 = (x1 << (r)) | (x1 >> (32 - (r))); x1 ^= x0; }
    TF_RND(13) TF_RND(15) TF_RND(26) TF_RND(6)
    x0 += k1;  x1 += ks2 + 1u;
    TF_RND(17) TF_RND(29) TF_RND(16) TF_RND(24)
    x0 += ks2; x1 += k0 + 2u;
    TF_RND(13) TF_RND(15) TF_RND(26) TF_RND(6)
    x0 += k0;  x1 += k1 + 3u;
    TF_RND(17) TF_RND(29) TF_RND(16) TF_RND(24)
    x0 += k1;  x1 += ks2 + 4u;
    TF_RND(13) TF_RND(15) TF_RND(26) TF_RND(6)
    x0 += ks2; x1 += k0 + 5u;
#undef TF_RND
    o0 = x0; o1 = x1;
}

// ===== software grid barrier =====
__device__ __forceinline__ void grid_barrier() {
    __syncthreads();
    if (threadIdx.x == 0) {
        __threadfence();
        unsigned gen = g_bar_gen;
        if (atomicAdd(&g_bar_count, 1u) == NBLK - 1) {
            atomicExch(&g_bar_count, 0u);
            __threadfence();
            g_bar_gen = gen + 1u;
        } else {
            while (g_bar_gen == gen) __nanosleep(32);
        }
        __threadfence();
    }
    __syncthreads();
}

// ===== weight blob packing (init) =====
__device__ void pack_blob(const float* __restrict__ W, int N, int TW,
                          unsigned char* __restrict__ blob, int gt, int gN) {
    const int PBv[6] = {0, 1, 0, 1, 2, 0};
    int units = N * 32;
    for (int u = gt; u < units; u += gN) {
        int n = u >> 5, kc = u & 31;
        const float* wp = W + (size_t)n * 512 + kc * 16;
        __align__(16) __nv_bfloat16 sp[3][16];
        #pragma unroll
        for (int i = 0; i < 16; i++) split3(wp[i], sp[0][i], sp[1][i], sp[2][i]);
        int ntile = n / TW, nl = n % TW;
        #pragma unroll
        for (int p = 0; p < 6; p++) {
            int vc = p * 32 + kc;
            unsigned char* d = blob + ((size_t)(ntile * 192 + vc) * TW + nl) * 32;
            const uint4* s4 = reinterpret_cast<const uint4*>(sp[PBv[p]]);
            *reinterpret_cast<uint4*>(d)      = s4[0];
            *reinterpret_cast<uint4*>(d + 16) = s4[1];
        }
    }
}

// ===== layer GEMM: C[64m x 192n] raw, virtual K = 3072, K=32/iter =====
__device__ void gemm_layer(const __nv_bfloat16* __restrict__ Abase, bool useEmb,
                           const unsigned char* __restrict__ blob,
                           float* __restrict__ Cdst,
                           int mt, int nt, SMem* sm) {
    const int tid = threadIdx.x;
    const int warp = tid >> 5, lane = tid & 31;
    const int mpart = warp >> 2, npart = warp & 3;   // 4 x 4 warps; warp = 16m x 48n
    const int m0 = mt * 64, n0 = nt * 192;

    const unsigned char* bBase = blob + (size_t)nt * 192 * LSTRIDE;

    // loader roles: unit0 = A (tid<256) or B (tid-256); unit1 = B (tid+256)
    const bool ldA = (tid < 256);
    int l0r, l0u;
    const __nv_bfloat16* aSrc = nullptr;
    if (ldA) {
        l0r = tid >> 2; l0u = tid & 3;
        int m = m0 + l0r;
        aSrc = useEmb ? Abase + (size_t)g_tok[m] * 512 : Abase + (size_t)m * 512;
    } else {
        int bu = tid - 256; l0r = bu >> 2; l0u = bu & 3;
    }
    const int l1r = (tid + 256) >> 2, l1u = (tid + 256) & 3;
    const int st0 = l0r * 32 + ((l0u ^ ((l0r >> 1) & 3)) * 8);
    const int st1 = l1r * 32 + ((l1u ^ ((l1r >> 1) & 3)) * 8);

    float acc[6][4];
    #pragma unroll
    for (int j = 0; j < 6; j++)
        #pragma unroll
        for (int q = 0; q < 4; q++) acc[j][q] = 0.f;

    uint32_t sAu = smem_u32(sm->A), sBu = smem_u32(sm->B);
    const int ar = mpart * 16 + (lane & 15);
    const int a_half = lane >> 4;
    const int br_base = npart * 48 + (lane & 7) + ((lane >> 4) << 3);
    const int b_half = (lane >> 3) & 1;

    uint4 pf0, pf1;
    {   // prologue vb=0
        if (ldA) {
            int vc = (l0u >> 1);
            int p = vc >> 5, kc = vc & 31, s = PA_of(p);
            pf0 = *reinterpret_cast<const uint4*>(aSrc + s * 262144 + kc * 16 + (l0u & 1) * 8);
        } else {
            int vc = (l0u >> 1);
            pf0 = *reinterpret_cast<const uint4*>(bBase + (size_t)vc * LSTRIDE + l0r * 32 + (l0u & 1) * 16);
        }
        int vc1 = (l1u >> 1);
        pf1 = *reinterpret_cast<const uint4*>(bBase + (size_t)vc1 * LSTRIDE + l1r * 32 + (l1u & 1) * 16);
    }

    #pragma unroll 2
    for (int vb = 0; vb < 96; vb++) {
        const int buf = vb & 1;
        if (ldA) *reinterpret_cast<uint4*>(sm->A + buf * 2048 + st0) = pf0;
        else     *reinterpret_cast<uint4*>(sm->B + buf * 6144 + st0) = pf0;
        *reinterpret_cast<uint4*>(sm->B + buf * 6144 + st1) = pf1;
        __syncthreads();

        if (vb + 1 < 96) {
            int vn = (vb + 1) * 2;
            if (ldA) {
                int vc = vn + (l0u >> 1);
                int p = vc >> 5, kc = vc & 31, s = PA_of(p);
                pf0 = *reinterpret_cast<const uint4*>(aSrc + s * 262144 + kc * 16 + (l0u & 1) * 8);
            } else {
                int vc = vn + (l0u >> 1);
                pf0 = *reinterpret_cast<const uint4*>(bBase + (size_t)vc * LSTRIDE + l0r * 32 + (l0u & 1) * 16);
            }
            int vc1 = vn + (l1u >> 1);
            pf1 = *reinterpret_cast<const uint4*>(bBase + (size_t)vc1 * LSTRIDE + l1r * 32 + (l1u & 1) * 16);
        }

        #pragma unroll
        for (int kc2 = 0; kc2 < 2; kc2++) {
            uint32_t aF[4];
            {
                int ua = kc2 * 2 + a_half;
                int up = ua ^ ((ar >> 1) & 3);
                ldsm4(aF, sAu + (buf * 2048 + ar * 32 + up * 8) * 2);
            }
            uint32_t bF[3][4];
            #pragma unroll
            for (int bt = 0; bt < 3; bt++) {
                int rb = br_base + bt * 16;
                int ub = kc2 * 2 + b_half;
                int up = ub ^ ((rb >> 1) & 3);
                ldsm4(bF[bt], sBu + (buf * 6144 + rb * 32 + up * 8) * 2);
            }
            #pragma unroll
            for (int bt = 0; bt < 3; bt++) {
                mma_bf16(acc[bt * 2 + 0], aF, &bF[bt][0]);
                mma_bf16(acc[bt * 2 + 1], aF, &bF[bt][2]);
            }
        }
    }

    // epilogue: raw C
    int row = m0 + mpart * 16 + (lane >> 2);
    #pragma unroll
    for (int j = 0; j < 6; j++) {
        int col = n0 + npart * 48 + j * 8 + (lane & 3) * 2;
        *reinterpret_cast<float2*>(Cdst + (size_t)row * 1536 + col) = make_float2(acc[j][0], acc[j][1]);
        *reinterpret_cast<float2*>(Cdst + (size_t)(row + 8) * 1536 + col) = make_float2(acc[j][2], acc[j][3]);
    }
    __syncthreads();
}

// ===== out GEMM: logits[32m x 64n] = h2 @ Wout^T + bout =====
__device__ void gemm_out(const __nv_bfloat16* __restrict__ Abase,
                         const unsigned char* __restrict__ blob,
                         const float* __restrict__ bout,
                         float* __restrict__ out, int t,
                         int mt, int nt, SMem* sm) {
    const int tid = threadIdx.x;
    const int warp = tid >> 5, lane = tid & 31;
    const int mpart = warp >> 3, npart = warp & 7;   // 2 x 8 warps; warp = 16m x 8n
    const int m0 = mt * 32, n0 = nt * 64;

    const unsigned char* bBase = blob + (size_t)nt * 192 * OSTRIDE;

    const bool ldA = (tid < 128);
    const bool ldB = (!ldA && tid < 384);
    int l0r = 0, l0u = 0;
    const __nv_bfloat16* aSrc = nullptr;
    if (ldA) {
        l0r = tid >> 2; l0u = tid & 3;
        aSrc = Abase + (size_t)(m0 + l0r) * 512;
    } else if (ldB) {
        int bu = tid - 128; l0r = bu >> 2; l0u = bu & 3;
    }
    const int st0 = l0r * 32 + ((l0u ^ ((l0r >> 1) & 3)) * 8);

    float acc[4] = {0.f, 0.f, 0.f, 0.f};

    uint32_t sAu = smem_u32(sm->A), sBu = smem_u32(sm->B);
    const int ar = mpart * 16 + (lane & 15);
    const int a_half = lane >> 4;
    const int lq = lane & 15;
    const int brq = npart * 8 + (lq & 7);
    const int b_half = lq >> 3;

    uint4 pf0;
    if (ldA) {
        int vc = (l0u >> 1);
        int p = vc >> 5, kc = vc & 31, s = PA_of(p);
        pf0 = *reinterpret_cast<const uint4*>(aSrc + s * 262144 + kc * 16 + (l0u & 1) * 8);
    } else if (ldB) {
        int vc = (l0u >> 1);
        pf0 = *reinterpret_cast<const uint4*>(bBase + (size_t)vc * OSTRIDE + l0r * 32 + (l0u & 1) * 16);
    }

    #pragma unroll 2
    for (int vb = 0; vb < 96; vb++) {
        const int buf = vb & 1;
        if (ldA) *reinterpret_cast<uint4*>(sm->A + buf * 1024 + st0) = pf0;
        else if (ldB) *reinterpret_cast<uint4*>(sm->B + buf * 2048 + st0) = pf0;
        __syncthreads();

        if (vb + 1 < 96) {
            int vn = (vb + 1) * 2;
            if (ldA) {
                int vc = vn + (l0u >> 1);
                int p = vc >> 5, kc = vc & 31, s = PA_of(p);
                pf0 = *reinterpret_cast<const uint4*>(aSrc + s * 262144 + kc * 16 + (l0u & 1) * 8);
            } else if (ldB) {
                int vc = vn + (l0u >> 1);
                pf0 = *reinterpret_cast<const uint4*>(bBase + (size_t)vc * OSTRIDE + l0r * 32 + (l0u & 1) * 16);
            }
        }

        #pragma unroll
        for (int kc2 = 0; kc2 < 2; kc2++) {
            uint32_t aF[4];
            {
                int ua = kc2 * 2 + a_half;
                int up = ua ^ ((ar >> 1) & 3);
                ldsm4(aF, sAu + (buf * 1024 + ar * 32 + up * 8) * 2);
            }
            uint32_t bF[2];
            {
                int ub = kc2 * 2 + b_half;
                int up = ub ^ ((brq >> 1) & 3);
                ldsm2(bF, sBu + (buf * 2048 + brq * 32 + up * 8) * 2);
            }
            mma_bf16(acc, aF, bF);
        }
    }

    int row = m0 + mpart * 16 + (lane >> 2);
    int col = n0 + npart * 8 + (lane & 3) * 2;
    float b0 = bout[col], b1 = bout[col + 1];
    float* o0 = out + (size_t)row * (Tdim * NCdim) + (size_t)t * NCdim + col;
    float* o1 = out + (size_t)(row + 8) * (Tdim * NCdim) + (size_t)t * NCdim + col;
    *reinterpret_cast<float2*>(o0) = make_float2(acc[0] + b0, acc[1] + b1);
    *reinterpret_cast<float2*>(o1) = make_float2(acc[2] + b0, acc[3] + b1);
    __syncthreads();
}

// ===== GRU combine (verified math) + split writes =====
__device__ void combine_stage(const float* __restrict__ bih, const float* __restrict__ bhh,
                              const float* __restrict__ Hprev, float* __restrict__ Hout,
                              __nv_bfloat16* __restrict__ Hsplit) {
    const int tid = threadIdx.x, bx = blockIdx.x;
    int base = bx * (Bdim * Hdim / NBLK);
    #pragma unroll 1
    for (int j = 0; j < (Bdim * Hdim / NBLK) / NTHR; j++) {
        int idx = base + j * NTHR + tid;
        int b = idx >> 9, h = idx & (Hdim - 1);
        const float* gib = g_gi + (size_t)b * (3 * Hdim);
        const float* ghb = g_gh + (size_t)b * (3 * Hdim);
        float ir = gib[h] + bih[h];
        float iz = gib[Hdim + h] + bih[Hdim + h];
        float in_ = gib[2 * Hdim + h] + bih[2 * Hdim + h];
        float hr = ghb[h] + bhh[h];
        float hz = ghb[Hdim + h] + bhh[Hdim + h];
        float hn = ghb[2 * Hdim + h] + bhh[2 * Hdim + h];
        float r = 1.f / (1.f + expf(-(ir + hr)));
        float z = 1.f / (1.f + expf(-(iz + hz)));
        float n = tanhf(in_ + r * hn);
        float hout = (1.f - z) * n + z * Hprev[idx];
        Hout[idx] = hout;
        __nv_bfloat16 s0, s1, s2;
        split3(hout, s0, s1, s2);
        Hsplit[idx] = s0;
        Hsplit[262144 + idx] = s1;
        Hsplit[2 * 262144 + idx] = s2;
    }
}

// ===== sample stage: 4 rows per block, 1 class/thread =====
__device__ void sample_stage(const float* __restrict__ out, float* __restrict__ tokout, int t, SMem* sm) {
    const int tid = threadIdx.x, bx = blockIdx.x;
    const int lane = tid & 31, warp = tid >> 5;
    unsigned key0 = g_key0[t], key1 = g_key1[t];
    #pragma unroll 1
    for (int i = 0; i < Bdim / NBLK; i++) {
        int b = bx + i * NBLK;
        const float* row = out + (size_t)b * Tdim * NCdim + (size_t)t * NCdim;
        float x = row[tid];

        float mx = x;
        #pragma unroll
        for (int o = 16; o; o >>= 1) mx = fmaxf(mx, __shfl_xor_sync(0xffffffffu, mx, o));
        if (lane == 0) sm->red[warp] = mx;
        __syncthreads();
        float m2 = sm->red[0];
        #pragma unroll
        for (int k = 1; k < 16; k++) m2 = fmaxf(m2, sm->red[k]);
        mx = m2;
        __syncthreads();

        float s = expf(x - mx);
        #pragma unroll
        for (int o = 16; o; o >>= 1) s += __shfl_xor_sync(0xffffffffu, s, o);
        if (lane == 0) sm->red[warp] = s;
        __syncthreads();
        float s2 = 0.f;
        #pragma unroll
        for (int k = 0; k < 16; k++) s2 += sm->red[k];
        float lse = logf(s2);
        __syncthreads();

        const float tiny = 1.17549435e-38f;
        unsigned j = (unsigned)(b * NCdim + tid);
        unsigned o0, o1;
        threefry2x32(key0, key1, 0u, j, o0, o1);
        unsigned bits = o0 ^ o1;
        float f = __uint_as_float((bits >> 9) | 0x3F800000u) - 1.0f;
        float u = fmaxf(tiny, f + tiny);
        float g = -logf(-logf(u));
        float best = ((x - mx) - lse) + g;
        int bi = tid;
        #pragma unroll
        for (int o = 16; o; o >>= 1) {
            float ov = __shfl_xor_sync(0xffffffffu, best, o);
            int   oi = __shfl_xor_sync(0xffffffffu, bi, o);
            if (ov > best || (ov == best && oi < bi)) { best = ov; bi = oi; }
        }
        if (lane == 0) { sm->val[warp] = best; sm->idx[warp] = bi; }
        __syncthreads();
        if (tid == 0) {
            float bv = sm->val[0]; int bidx = sm->idx[0];
            #pragma unroll
            for (int k = 1; k < 16; k++) {
                if (sm->val[k] > bv || (sm->val[k] == bv && sm->idx[k] < bidx)) {
                    bv = sm->val[k]; bidx = sm->idx[k];
                }
            }
            g_tok[b] = bidx;
            if (tokout) tokout[(size_t)b * Tdim + t] = (float)bidx;
        }
        __syncthreads();
    }
}

// ===== main persistent kernel =====
__global__ void __launch_bounds__(NTHR, 1)
prior_mma(const float* __restrict__ note, const float* __restrict__ genre,
          const float* __restrict__ Whid, const float* __restrict__ bhid,
          const float* __restrict__ emb,
          const float* __restrict__ Wih1, const float* __restrict__ Whh1,
          const float* __restrict__ bih1, const float* __restrict__ bhh1,
          const float* __restrict__ Wih2, const float* __restrict__ Whh2,
          const float* __restrict__ bih2, const float* __restrict__ bhh2,
          const float* __restrict__ Wout, const float* __restrict__ bout,
          float* __restrict__ out, float* __restrict__ tokout) {
    __shared__ SMem sm;
    const int tid = threadIdx.x, bx = blockIdx.x;

    // ---------- init ----------
    {
        int gt = bx * NTHR + tid, gN = NBLK * NTHR;
        if (gt < Tdim) {
            unsigned o0, o1;
            threefry2x32(0u, 42u, 0u, (unsigned)gt, o0, o1);
            g_key0[gt] = o0; g_key1[gt] = o1;
        }
        if (gt < Bdim) g_tok[gt] = 0;

        pack_blob(Wih1, 1536, 192, g_blob_ih1, gt, gN);
        pack_blob(Whh1, 1536, 192, g_blob_hh1, gt, gN);
        pack_blob(Wih2, 1536, 192, g_blob_ih2, gt, gN);
        pack_blob(Whh2, 1536, 192, g_blob_hh2, gt, gN);
        pack_blob(Wout, 512, 64, g_blob_out, gt, gN);

        for (int idx = gt; idx < 512 * 512; idx += gN) {
            __nv_bfloat16 s0, s1, s2;
            split3(emb[idx], s0, s1, s2);
            g_embsplit[idx] = s0;
            g_embsplit[262144 + idx] = s1;
            g_embsplit[2 * 262144 + idx] = s2;
        }

        for (int r = 0; r < Bdim / NBLK; r++) {
            int b = bx * (Bdim / NBLK) + r;
            for (int i = tid; i < SKELdim; i += NTHR) sm.init[i] = note[b * SKELdim + i];
            for (int i = tid; i < GENdim; i += NTHR) sm.init[SKELdim + i] = genre[b * GENdim + i];
            __syncthreads();
            for (int j = tid; j < Hdim; j += NTHR) {
                const float* w = Whid + (size_t)j * (SKELdim + GENdim);
                float acc = 0.f;
                #pragma unroll 8
                for (int k = 0; k < SKELdim + GENdim; k++) acc = fmaf(sm.init[k], w[k], acc);
                acc += bhid[j];
                int idx = b * Hdim + j;
                g_h1[idx] = acc;
                __nv_bfloat16 s0, s1, s2;
                split3(acc, s0, s1, s2);
                g_h1split[idx] = s0;
                g_h1split[262144 + idx] = s1;
                g_h1split[2 * 262144 + idx] = s2;
            }
            __syncthreads();
        }
    }
    grid_barrier();

    const bool isGh = (bx >= 64);
    const int rj = bx & 63;
    const int mt = rj >> 3, nt = rj & 7;
    const int omt = bx >> 3, ont = bx & 7;

    for (int t = 0; t < Tdim; t++) {
        // ---- layer 1 ----
        gemm_layer(isGh ? g_h1split : g_embsplit, !isGh,
                   isGh ? g_blob_hh1 : g_blob_ih1,
                   isGh ? g_gh : g_gi, mt, nt, &sm);
        grid_barrier();
        combine_stage(bih1, bhh1, g_h1, g_h1, g_h1split);
        grid_barrier();

        // ---- layer 2 ----
        const __nv_bfloat16* a2 = isGh ? ((t == 0) ? g_h1split : g_h2split) : g_h1split;
        gemm_layer(a2, false,
                   isGh ? g_blob_hh2 : g_blob_ih2,
                   isGh ? g_gh : g_gi, mt, nt, &sm);
        grid_barrier();
        combine_stage(bih2, bhh2, (t == 0) ? g_h1 : g_h2, g_h2, g_h2split);
        grid_barrier();

        // ---- out GEMM (all 128 CTAs) ----
        gemm_out(g_h2split, g_blob_out, bout, out, t, omt, ont, &sm);
        grid_barrier();

        sample_stage(out, tokout, t, &sm);
        grid_barrier();
    }
}

// ===== launch: ONE graph node =====
extern "C" void kernel_launch(void* const* d_in, const int* in_sizes, int n_in,
                              void* d_out, int out_size) {
    const float* note  = (const float*)d_in[1];
    const float* genre = (const float*)d_in[2];
    const float* W_hid = (const float*)d_in[3];
    const float* b_hid = (const float*)d_in[4];
    const float* emb   = (const float*)d_in[5];
    const float* W_ih1 = (const float*)d_in[6];
    const float* W_hh1 = (const float*)d_in[7];
    const float* b_ih1 = (const float*)d_in[8];
    const float* b_hh1 = (const float*)d_in[9];
    const float* W_ih2 = (const float*)d_in[10];
    const float* W_hh2 = (const float*)d_in[11];
    const float* b_ih2 = (const float*)d_in[12];
    const float* b_hh2 = (const float*)d_in[13];
    const float* W_out = (const float*)d_in[14];
    const float* b_out = (const float*)d_in[15];

    float* out = (float*)d_out;
    const long long need = (long long)Bdim * Tdim * NCdim + (long long)Bdim * Tdim;
    float* tokout = ((long long)out_size >= need) ? (out + (size_t)Bdim * Tdim * NCdim) : nullptr;

    prior_mma<<<NBLK, NTHR>>>(note, genre, W_hid, b_hid, emb,
                              W_ih1, W_hh1, b_ih1, b_hh1,
                              W_ih2, W_hh2, b_ih2, b_hh2,
                              W_out, b_out, out, tokout);
}

// round 12
// speedup vs baseline: 1.6103x; 1.0137x over previous
#include <cuda_runtime.h>
#include <cuda_bf16.h>
#include <stdint.h>
#include <math.h>

// ===== problem dims =====
#define Bdim 512
#define Tdim 256
#define Hdim 512
#define NCdim 512
#define SKELdim 256
#define GENdim 16

#define NBLK 128
#define NTHR 512

typedef unsigned long long ull;

// ===== persistent device state =====
__device__ float g_h1[2][Bdim * Hdim];
__device__ float g_h2[2][Bdim * Hdim];
__device__ ull   g_winner[2][Bdim];
__device__ unsigned g_key0[Tdim];
__device__ unsigned g_key1[Tdim];
__device__ unsigned g_bar_count;
__device__ volatile unsigned g_bar_gen;

// bf16 split activations [3][512][512] (ping-pong for h1/h2)
__device__ __align__(16) __nv_bfloat16 g_embsplit[3 * 262144];
__device__ __align__(16) __nv_bfloat16 g_h1s[2][3 * 262144];
__device__ __align__(16) __nv_bfloat16 g_h2s[2][3 * 262144];

// weight blobs
// layer (fused gi+gh tiles): [16 nt][192 vc][96 rows][32B]  (row = hl*3+g, 16 bf16 = 32B)
#define LBLOB (16 * 192 * 96 * 32)
__device__ __align__(16) unsigned char g_blob_ih1[LBLOB];
__device__ __align__(16) unsigned char g_blob_hh1[LBLOB];
__device__ __align__(16) unsigned char g_blob_ih2[LBLOB];
__device__ __align__(16) unsigned char g_blob_hh2[LBLOB];
// out: [8 nt][192 vc][64 rows][32B]
#define OBLOB (8 * 192 * 64 * 32)
__device__ __align__(16) unsigned char g_blob_out[OBLOB];

// ===== shared =====
__shared__ __align__(16) char smem_raw[41216];

// ===== helpers =====
__device__ __forceinline__ uint32_t smem_u32(const void* p) {
    uint32_t a;
    asm("{ .reg .u64 tmp; cvta.to.shared.u64 tmp, %1; cvt.u32.u64 %0, tmp; }" : "=r"(a) : "l"(p));
    return a;
}
__device__ __forceinline__ void ldsm4(uint32_t* r, uint32_t addr) {
    asm volatile("ldmatrix.sync.aligned.m8n8.x4.shared.b16 {%0,%1,%2,%3}, [%4];"
                 : "=r"(r[0]), "=r"(r[1]), "=r"(r[2]), "=r"(r[3]) : "r"(addr));
}
__device__ __forceinline__ void ldsm2(uint32_t* r, uint32_t addr) {
    asm volatile("ldmatrix.sync.aligned.m8n8.x2.shared.b16 {%0,%1}, [%2];"
                 : "=r"(r[0]), "=r"(r[1]) : "r"(addr));
}
__device__ __forceinline__ void mma_bf16(float* c, const uint32_t* a, const uint32_t* b) {
    asm volatile("mma.sync.aligned.m16n8k16.row.col.f32.bf16.bf16.f32 "
                 "{%0,%1,%2,%3}, {%4,%5,%6,%7}, {%8,%9}, {%0,%1,%2,%3};"
                 : "+f"(c[0]), "+f"(c[1]), "+f"(c[2]), "+f"(c[3])
                 : "r"(a[0]), "r"(a[1]), "r"(a[2]), "r"(a[3]), "r"(b[0]), "r"(b[1]));
}
__device__ __forceinline__ void split3(float x, __nv_bfloat16& b0, __nv_bfloat16& b1, __nv_bfloat16& b2) {
    b0 = __float2bfloat16_rn(x);
    float r1 = x - __bfloat162float(b0);
    b1 = __float2bfloat16_rn(r1);
    b2 = __float2bfloat16_rn(r1 - __bfloat162float(b1));
}
__device__ __forceinline__ int PA_of(int p) { return (p == 2 || p == 3) ? 1 : (p == 5 ? 2 : 0); }
__device__ __forceinline__ uint32_t fkey(float v) {
    uint32_t u = __float_as_uint(v);
    return (u & 0x80000000u) ? ~u : (u | 0x80000000u);
}
__device__ __forceinline__ int win_decode(ull w) { return 511 - (int)(w & 511ull); }

// ===== threefry2x32 =====
__device__ __forceinline__ void threefry2x32(unsigned k0, unsigned k1,
                                             unsigned c0, unsigned c1,
                                             unsigned& o0, unsigned& o1) {
    unsigned ks2 = k0 ^ k1 ^ 0x1BD11BDAu;
    unsigned x0 = c0 + k0;
    unsigned x1 = c1 + k1;
#define TF_RND(r) { x0 += x1; x1 = (x1 << (r)) | (x1 >> (32 - (r))); x1 ^= x0; }
    TF_RND(13) TF_RND(15) TF_RND(26) TF_RND(6)
    x0 += k1;  x1 += ks2 + 1u;
    TF_RND(17) TF_RND(29) TF_RND(16) TF_RND(24)
    x0 += ks2; x1 += k0 + 2u;
    TF_RND(13) TF_RND(15) TF_RND(26) TF_RND(6)
    x0 += k0;  x1 += k1 + 3u;
    TF_RND(17) TF_RND(29) TF_RND(16) TF_RND(24)
    x0 += k1;  x1 += ks2 + 4u;
    TF_RND(13) TF_RND(15) TF_RND(26) TF_RND(6)
    x0 += ks2; x1 += k0 + 5u;
#undef TF_RND
    o0 = x0; o1 = x1;
}
__device__ __forceinline__ float gumbel_of(unsigned key0, unsigned key1, unsigned j) {
    unsigned o0, o1;
    threefry2x32(key0, key1, 0u, j, o0, o1);
    unsigned bits = o0 ^ o1;
    const float tiny = 1.17549435e-38f;
    float f = __uint_as_float((bits >> 9) | 0x3F800000u) - 1.0f;
    float u = fmaxf(tiny, f + tiny);
    return -logf(-logf(u));
}

// ===== software grid barrier =====
__device__ __forceinline__ void grid_barrier() {
    __syncthreads();
    if (threadIdx.x == 0) {
        __threadfence();
        unsigned gen = g_bar_gen;
        if (atomicAdd(&g_bar_count, 1u) == NBLK - 1) {
            atomicExch(&g_bar_count, 0u);
            __threadfence();
            g_bar_gen = gen + 1u;
        } else {
            while (g_bar_gen == gen) __nanosleep(32);
        }
        __threadfence();
    }
    __syncthreads();
}

// ===== blob packing =====
__device__ void pack_blob_fused(const float* __restrict__ W, unsigned char* __restrict__ blob,
                                int gt, int gN) {
    const int PBv[6] = {0, 1, 0, 1, 2, 0};
    for (int u = gt; u < 1536 * 32; u += gN) {
        int nw = u >> 5, kc = u & 31;
        const float* wp = W + (size_t)nw * 512 + kc * 16;
        __align__(16) __nv_bfloat16 sp[3][16];
        #pragma unroll
        for (int i = 0; i < 16; i++) split3(wp[i], sp[0][i], sp[1][i], sp[2][i]);
        int g = nw >> 9, h = nw & 511, nt = h >> 5, hl = h & 31;
        int pr = hl * 3 + g;
        #pragma unroll
        for (int p = 0; p < 6; p++) {
            int vc = p * 32 + kc;
            unsigned char* d = blob + ((size_t)(nt * 192 + vc) * 96 + pr) * 32;
            const uint4* s4 = reinterpret_cast<const uint4*>(sp[PBv[p]]);
            *reinterpret_cast<uint4*>(d)      = s4[0];
            *reinterpret_cast<uint4*>(d + 16) = s4[1];
        }
    }
}
__device__ void pack_blob_out(const float* __restrict__ W, unsigned char* __restrict__ blob,
                              int gt, int gN) {
    const int PBv[6] = {0, 1, 0, 1, 2, 0};
    for (int u = gt; u < 512 * 32; u += gN) {
        int n = u >> 5, kc = u & 31;
        const float* wp = W + (size_t)n * 512 + kc * 16;
        __align__(16) __nv_bfloat16 sp[3][16];
        #pragma unroll
        for (int i = 0; i < 16; i++) split3(wp[i], sp[0][i], sp[1][i], sp[2][i]);
        int nt = n >> 6, nl = n & 63;
        #pragma unroll
        for (int p = 0; p < 6; p++) {
            int vc = p * 32 + kc;
            unsigned char* d = blob + ((size_t)(nt * 192 + vc) * 64 + nl) * 32;
            const uint4* s4 = reinterpret_cast<const uint4*>(sp[PBv[p]]);
            *reinterpret_cast<uint4*>(d)      = s4[0];
            *reinterpret_cast<uint4*>(d + 16) = s4[1];
        }
    }
}

// ===== fused layer stage: dual gemm (gi,gh) 64m x 96n + in-block GRU combine =====
// Ax: x-activation splits (emb gather if useWin), Ah: h-activation splits.
// Bi/Bh: fused blobs. Hprev/Hout: float h state. Hsplit: output splits.
__device__ void layer_stage(const __nv_bfloat16* __restrict__ Ax, bool useWin, int slot,
                            const __nv_bfloat16* __restrict__ Ah,
                            const unsigned char* __restrict__ Bi,
                            const unsigned char* __restrict__ Bh,
                            const float* __restrict__ bih, const float* __restrict__ bhh,
                            const float* __restrict__ Hprev, float* __restrict__ Hout,
                            __nv_bfloat16* __restrict__ Hsplit) {
    const int tid = threadIdx.x, bx = blockIdx.x;
    const int mt = bx >> 4, nt = bx & 15;
    const int m0 = mt * 64;
    __nv_bfloat16* sA = (__nv_bfloat16*)smem_raw;             // [2][2][64][32]
    __nv_bfloat16* sB = (__nv_bfloat16*)(smem_raw + 16384);   // [2][2][96][32]

    const int warp = tid >> 5, lane = tid & 31;
    const int role = warp >> 3;            // 0: gi, 1: gh
    const int w8 = warp & 7;
    const int mpart = w8 >> 1, npart = w8 & 1;

    // ---- loader unit setup ----
    // unit0 (A): all threads. roleA = tid>>8, rowA = (tid>>2)&63, kuA = tid&3
    const int roleA = tid >> 8, rowA = (tid >> 2) & 63, kuA = tid & 3;
    const __nv_bfloat16* aBase;
    if (roleA == 0) {
        int m = m0 + rowA;
        int tok = useWin ? win_decode(g_winner[slot][m]) : 0;
        aBase = useWin ? (Ax + (size_t)tok * 512) : (Ax + (size_t)m * 512);
    } else {
        aBase = Ah + (size_t)(m0 + rowA) * 512;
    }
    const int aSt = roleA * 2048 + rowA * 32 + ((kuA ^ ((rowA >> 1) & 3)) * 8);
    // unit1 (B): v = tid (0..511): roleB1 = v>=384, rowB1, kuB1
    const int v1 = tid;
    const int roleB1 = (v1 >= 384) ? 1 : 0;
    const int rv1 = v1 - roleB1 * 384;
    const int rowB1 = rv1 >> 2, kuB1 = rv1 & 3;
    const unsigned char* bBase1 = (roleB1 ? Bh : Bi) + (size_t)nt * 192 * 3072;
    const int bSt1 = roleB1 * 3072 + rowB1 * 32 + ((kuB1 ^ ((rowB1 >> 1) & 3)) * 8);
    // unit2 (B, tid<256): v = 512+tid: role 1, rows 32..95
    const bool hasU2 = (tid < 256);
    const int rv2 = (512 + tid) - 384;
    const int rowB2 = rv2 >> 2, kuB2 = rv2 & 3;
    const unsigned char* bBase2 = Bh + (size_t)nt * 192 * 3072;
    const int bSt2 = 3072 + rowB2 * 32 + ((kuB2 ^ ((rowB2 >> 1) & 3)) * 8);

    float acc[6][4];
    #pragma unroll
    for (int j = 0; j < 6; j++)
        #pragma unroll
        for (int q = 0; q < 4; q++) acc[j][q] = 0.f;

    uint32_t sAu = smem_u32(sA), sBu = smem_u32(sB);
    const int ar = mpart * 16 + (lane & 15);
    const int a_half = lane >> 4;
    const int br_base = npart * 48 + (lane & 7) + ((lane >> 4) << 3);
    const int b_half = (lane >> 3) & 1;

    uint4 pf0, pf1, pf2;
    {   // prologue vb=0
        int vcA = (kuA >> 1);
        int pA = vcA >> 5, sA3 = PA_of(pA);
        pf0 = *reinterpret_cast<const uint4*>(aBase + sA3 * 262144 + (vcA & 31) * 16 + (kuA & 1) * 8);
        int vc1 = (kuB1 >> 1);
        pf1 = *reinterpret_cast<const uint4*>(bBase1 + (size_t)vc1 * 3072 + rowB1 * 32 + (kuB1 & 1) * 16);
        if (hasU2) {
            int vc2 = (kuB2 >> 1);
            pf2 = *reinterpret_cast<const uint4*>(bBase2 + (size_t)vc2 * 3072 + rowB2 * 32 + (kuB2 & 1) * 16);
        }
    }

    #pragma unroll 2
    for (int vb = 0; vb < 96; vb++) {
        const int buf = vb & 1;
        *reinterpret_cast<uint4*>(sA + buf * 4096 + aSt) = pf0;
        *reinterpret_cast<uint4*>(sB + buf * 6144 + bSt1) = pf1;
        if (hasU2) *reinterpret_cast<uint4*>(sB + buf * 6144 + bSt2) = pf2;
        __syncthreads();

        if (vb + 1 < 96) {
            int vn = (vb + 1) * 2;
            int vcA = vn + (kuA >> 1);
            int pA = vcA >> 5, sA3 = PA_of(pA);
            pf0 = *reinterpret_cast<const uint4*>(aBase + sA3 * 262144 + (vcA & 31) * 16 + (kuA & 1) * 8);
            int vc1 = vn + (kuB1 >> 1);
            pf1 = *reinterpret_cast<const uint4*>(bBase1 + (size_t)vc1 * 3072 + rowB1 * 32 + (kuB1 & 1) * 16);
            if (hasU2) {
                int vc2 = vn + (kuB2 >> 1);
                pf2 = *reinterpret_cast<const uint4*>(bBase2 + (size_t)vc2 * 3072 + rowB2 * 32 + (kuB2 & 1) * 16);
            }
        }

        #pragma unroll
        for (int kc2 = 0; kc2 < 2; kc2++) {
            uint32_t aF[4];
            {
                int ua = kc2 * 2 + a_half;
                int up = ua ^ ((ar >> 1) & 3);
                ldsm4(aF, sAu + (buf * 4096 + role * 2048 + ar * 32 + up * 8) * 2);
            }
            uint32_t bF[3][4];
            #pragma unroll
            for (int bt = 0; bt < 3; bt++) {
                int rb = br_base + bt * 16;
                int ub = kc2 * 2 + b_half;
                int up = ub ^ ((rb >> 1) & 3);
                ldsm4(bF[bt], sBu + (buf * 6144 + role * 3072 + rb * 32 + up * 8) * 2);
            }
            #pragma unroll
            for (int bt = 0; bt < 3; bt++) {
                mma_bf16(acc[bt * 2 + 0], aF, &bF[bt][0]);
                mma_bf16(acc[bt * 2 + 1], aF, &bF[bt][2]);
            }
        }
    }

    // ---- epilogue: two half-m passes, combine in-block ----
    float* stg = (float*)smem_raw;   // [2 role][32][96] = 24KB
    #pragma unroll 1
    for (int ph = 0; ph < 2; ph++) {
        __syncthreads();
        if ((mpart >> 1) == ph) {
            int ml = (mpart & 1) * 16 + (lane >> 2);
            #pragma unroll
            for (int j = 0; j < 6; j++) {
                int col = npart * 48 + j * 8 + (lane & 3) * 2;
                stg[role * 3072 + ml * 96 + col]     = acc[j][0];
                stg[role * 3072 + ml * 96 + col + 1] = acc[j][1];
                stg[role * 3072 + (ml + 8) * 96 + col]     = acc[j][2];
                stg[role * 3072 + (ml + 8) * 96 + col + 1] = acc[j][3];
            }
        }
        __syncthreads();
        #pragma unroll
        for (int q = 0; q < 2; q++) {
            int e = tid + q * 512;
            int ml = e >> 5, hl = e & 31;
            int m = m0 + ph * 32 + ml;
            int h = nt * 32 + hl;
            float ir  = stg[ml * 96 + hl * 3 + 0] + bih[h];
            float iz  = stg[ml * 96 + hl * 3 + 1] + bih[512 + h];
            float in_ = stg[ml * 96 + hl * 3 + 2] + bih[1024 + h];
            float hr  = stg[3072 + ml * 96 + hl * 3 + 0] + bhh[h];
            float hz  = stg[3072 + ml * 96 + hl * 3 + 1] + bhh[512 + h];
            float hn  = stg[3072 + ml * 96 + hl * 3 + 2] + bhh[1024 + h];
            float r = 1.f / (1.f + expf(-(ir + hr)));
            float z = 1.f / (1.f + expf(-(iz + hz)));
            float n = tanhf(in_ + r * hn);
            float hout = (1.f - z) * n + z * Hprev[(size_t)m * 512 + h];
            Hout[(size_t)m * 512 + h] = hout;
            __nv_bfloat16 s0, s1, s2;
            split3(hout, s0, s1, s2);
            int idx = m * 512 + h;
            Hsplit[idx] = s0;
            Hsplit[262144 + idx] = s1;
            Hsplit[2 * 262144 + idx] = s2;
        }
    }
    __syncthreads();
}

// ===== out stage: logits gemm 32m x 64n + bias + gumbel argmax atomics =====
__device__ void out_stage(const __nv_bfloat16* __restrict__ Abase,
                          const float* __restrict__ bout,
                          float* __restrict__ out, int t, int wslot) {
    const int tid = threadIdx.x, bx = blockIdx.x;
    const int warp = tid >> 5, lane = tid & 31;
    const int mpart = warp >> 3, npart = warp & 7;
    const int omt = bx >> 3, ont = bx & 7;
    const int m0 = omt * 32, n0 = ont * 64;
    __nv_bfloat16* sA = (__nv_bfloat16*)smem_raw;            // [2][32][32]
    __nv_bfloat16* sB = (__nv_bfloat16*)(smem_raw + 4096);   // [2][64][32]

    const unsigned char* bBase = g_blob_out + (size_t)ont * 192 * 2048;

    const bool ldA = (tid < 128);
    const bool ldB = (!ldA && tid < 384);
    int l0r = 0, l0u = 0;
    const __nv_bfloat16* aSrc = nullptr;
    if (ldA) {
        l0r = tid >> 2; l0u = tid & 3;
        aSrc = Abase + (size_t)(m0 + l0r) * 512;
    } else if (ldB) {
        int bu = tid - 128; l0r = bu >> 2; l0u = bu & 3;
    }
    const int st0 = l0r * 32 + ((l0u ^ ((l0r >> 1) & 3)) * 8);

    float acc[4] = {0.f, 0.f, 0.f, 0.f};

    uint32_t sAu = smem_u32(sA), sBu = smem_u32(sB);
    const int ar = mpart * 16 + (lane & 15);
    const int a_half = lane >> 4;
    const int lq = lane & 15;
    const int brq = npart * 8 + (lq & 7);
    const int b_half = lq >> 3;

    uint4 pf0;
    if (ldA) {
        int vc = (l0u >> 1);
        int p = vc >> 5, s = PA_of(p);
        pf0 = *reinterpret_cast<const uint4*>(aSrc + s * 262144 + (vc & 31) * 16 + (l0u & 1) * 8);
    } else if (ldB) {
        int vc = (l0u >> 1);
        pf0 = *reinterpret_cast<const uint4*>(bBase + (size_t)vc * 2048 + l0r * 32 + (l0u & 1) * 16);
    }

    #pragma unroll 2
    for (int vb = 0; vb < 96; vb++) {
        const int buf = vb & 1;
        if (ldA) *reinterpret_cast<uint4*>(sA + buf * 1024 + st0) = pf0;
        else if (ldB) *reinterpret_cast<uint4*>(sB + buf * 2048 + st0) = pf0;
        __syncthreads();

        if (vb + 1 < 96) {
            int vn = (vb + 1) * 2;
            if (ldA) {
                int vc = vn + (l0u >> 1);
                int p = vc >> 5, s = PA_of(p);
                pf0 = *reinterpret_cast<const uint4*>(aSrc + s * 262144 + (vc & 31) * 16 + (l0u & 1) * 8);
            } else if (ldB) {
                int vc = vn + (l0u >> 1);
                pf0 = *reinterpret_cast<const uint4*>(bBase + (size_t)vc * 2048 + l0r * 32 + (l0u & 1) * 16);
            }
        }

        #pragma unroll
        for (int kc2 = 0; kc2 < 2; kc2++) {
            uint32_t aF[4];
            {
                int ua = kc2 * 2 + a_half;
                int up = ua ^ ((ar >> 1) & 3);
                ldsm4(aF, sAu + (buf * 1024 + ar * 32 + up * 8) * 2);
            }
            uint32_t bF[2];
            {
                int ub = kc2 * 2 + b_half;
                int up = ub ^ ((brq >> 1) & 3);
                ldsm2(bF, sBu + (buf * 2048 + brq * 32 + up * 8) * 2);
            }
            mma_bf16(acc, aF, bF);
        }
    }

    // epilogue: bias, write logits, gumbel argmax atomics
    const int row0 = m0 + mpart * 16 + (lane >> 2);
    const int col0 = n0 + npart * 8 + (lane & 3) * 2;
    const float b0 = bout[col0], b1 = bout[col0 + 1];
    float v00 = acc[0] + b0, v01 = acc[1] + b1;   // row0
    float v10 = acc[2] + b0, v11 = acc[3] + b1;   // row0+8
    float* o0 = out + (size_t)row0 * (Tdim * NCdim) + (size_t)t * NCdim + col0;
    float* o1 = out + (size_t)(row0 + 8) * (Tdim * NCdim) + (size_t)t * NCdim + col0;
    *reinterpret_cast<float2*>(o0) = make_float2(v00, v01);
    *reinterpret_cast<float2*>(o1) = make_float2(v10, v11);

    unsigned key0 = g_key0[t], key1 = g_key1[t];
    #pragma unroll
    for (int rr = 0; rr < 2; rr++) {
        int row = row0 + rr * 8;
        float va = (rr ? v10 : v00) + gumbel_of(key0, key1, (unsigned)(row * 512 + col0));
        float vb = (rr ? v11 : v01) + gumbel_of(key0, key1, (unsigned)(row * 512 + col0 + 1));
        ull ka = ((ull)fkey(va) << 32) | (ull)(511 - col0);
        ull kb = ((ull)fkey(vb) << 32) | (ull)(511 - (col0 + 1));
        ull kr = (ka >= kb) ? ka : kb;
        #pragma unroll
        for (int o = 1; o <= 2; o <<= 1) {
            ull other = __shfl_xor_sync(0xffffffffu, kr, o);
            if (other > kr) kr = other;
        }
        if ((lane & 3) == 0) atomicMax(&g_winner[wslot][row], kr);
    }
    __syncthreads();
}

// ===== main persistent kernel =====
__global__ void __launch_bounds__(NTHR, 1)
prior_mma(const float* __restrict__ note, const float* __restrict__ genre,
          const float* __restrict__ Whid, const float* __restrict__ bhid,
          const float* __restrict__ emb,
          const float* __restrict__ Wih1, const float* __restrict__ Whh1,
          const float* __restrict__ bih1, const float* __restrict__ bhh1,
          const float* __restrict__ Wih2, const float* __restrict__ Whh2,
          const float* __restrict__ bih2, const float* __restrict__ bhh2,
          const float* __restrict__ Wout, const float* __restrict__ bout,
          float* __restrict__ out, float* __restrict__ tokout) {
    const int tid = threadIdx.x, bx = blockIdx.x;
    const int gt = bx * NTHR + tid;
    const int gN = NBLK * NTHR;

    // ---------- init ----------
    {
        if (gt < Tdim) {
            unsigned o0, o1;
            threefry2x32(0u, 42u, 0u, (unsigned)gt, o0, o1);
            g_key0[gt] = o0; g_key1[gt] = o1;
        }
        if (gt < Bdim) {
            g_winner[0][gt] = 0ull;
            g_winner[1][gt] = 511ull;   // decodes to tok=0 for step 0
        }

        pack_blob_fused(Wih1, g_blob_ih1, gt, gN);
        pack_blob_fused(Whh1, g_blob_hh1, gt, gN);
        pack_blob_fused(Wih2, g_blob_ih2, gt, gN);
        pack_blob_fused(Whh2, g_blob_hh2, gt, gN);
        pack_blob_out(Wout, g_blob_out, gt, gN);

        for (int idx = gt; idx < 262144; idx += gN) {
            __nv_bfloat16 s0, s1, s2;
            split3(emb[idx], s0, s1, s2);
            g_embsplit[idx] = s0;
            g_embsplit[262144 + idx] = s1;
            g_embsplit[2 * 262144 + idx] = s2;
        }

        float* sInit = (float*)smem_raw;
        for (int r = 0; r < Bdim / NBLK; r++) {
            int b = bx * (Bdim / NBLK) + r;
            for (int i = tid; i < SKELdim; i += NTHR) sInit[i] = note[b * SKELdim + i];
            for (int i = tid; i < GENdim; i += NTHR) sInit[SKELdim + i] = genre[b * GENdim + i];
            __syncthreads();
            for (int j = tid; j < Hdim; j += NTHR) {
                const float* w = Whid + (size_t)j * (SKELdim + GENdim);
                float acc = 0.f;
                #pragma unroll 8
                for (int k = 0; k < SKELdim + GENdim; k++) acc = fmaf(sInit[k], w[k], acc);
                acc += bhid[j];
                int idx = b * Hdim + j;
                g_h1[0][idx] = acc;
                __nv_bfloat16 s0, s1, s2;
                split3(acc, s0, s1, s2);
                g_h1s[0][idx] = s0;
                g_h1s[0][262144 + idx] = s1;
                g_h1s[0][2 * 262144 + idx] = s2;
            }
            __syncthreads();
        }
    }
    grid_barrier();

    for (int t = 0; t < Tdim; t++) {
        const int rp = t & 1, wp = rp ^ 1;
        const int rslot = (t + 1) & 1;   // winner slot holding sample of step t-1

        // tokout for step t-1 (CTA 0)
        if (t > 0 && bx == 0 && tokout) {
            tokout[(size_t)tid * Tdim + (t - 1)] = (float)win_decode(g_winner[rslot][tid]);
        }

        // ---- stage 1: layer1 dual gemm + combine -> h1[wp] ----
        layer_stage(g_embsplit, true, rslot,
                    g_h1s[rp], g_blob_ih1, g_blob_hh1,
                    bih1, bhh1, g_h1[rp], g_h1[wp], g_h1s[wp]);
        grid_barrier();

        // ---- stage 2: layer2 dual gemm + combine -> h2[wp] (+ winner slot reset) ----
        if (bx == 1 && tid < 512) g_winner[rslot][tid] = 0ull;
        layer_stage(g_h1s[wp], false, 0,
                    (t == 0) ? g_h1s[wp] : g_h2s[rp],
                    g_blob_ih2, g_blob_hh2,
                    bih2, bhh2,
                    (t == 0) ? g_h1[wp] : g_h2[rp],
                    g_h2[wp], g_h2s[wp]);
        grid_barrier();

        // ---- stage 3: out gemm + gumbel argmax -> winner[t&1] ----
        out_stage(g_h2s[wp], bout, out, t, t & 1);
        grid_barrier();
    }

    // final tokout for t=255 (winner slot (256+1)&1 = 1)
    if (bx == 0 && tokout) {
        tokout[(size_t)tid * Tdim + (Tdim - 1)] = (float)win_decode(g_winner[1][tid]);
    }
}

// ===== launch: ONE graph node =====
extern "C" void kernel_launch(void* const* d_in, const int* in_sizes, int n_in,
                              void* d_out, int out_size) {
    const float* note  = (const float*)d_in[1];
    const float* genre = (const float*)d_in[2];
    const float* W_hid = (const float*)d_in[3];
    const float* b_hid = (const float*)d_in[4];
    const float* emb   = (const float*)d_in[5];
    const float* W_ih1 = (const float*)d_in[6];
    const float* W_hh1 = (const float*)d_in[7];
    const float* b_ih1 = (const float*)d_in[8];
    const float* b_hh1 = (const float*)d_in[9];
    const float* W_ih2 = (const float*)d_in[10];
    const float* W_hh2 = (const float*)d_in[11];
    const float* b_ih2 = (const float*)d_in[12];
    const float* b_hh2 = (const float*)d_in[13];
    const float* W_out = (const float*)d_in[14];
    const float* b_out = (const float*)d_in[15];

    float* out = (float*)d_out;
    const long long need = (long long)Bdim * Tdim * NCdim + (long long)Bdim * Tdim;
    float* tokout = ((long long)out_size >= need) ? (out + (size_t)Bdim * Tdim * NCdim) : nullptr;

    prior_mma<<<NBLK, NTHR>>>(note, genre, W_hid, b_hid, emb,
                              W_ih1, W_hh1, b_ih1, b_hh1,
                              W_ih2, W_hh2, b_ih2, b_hh2,
                              W_out, b_out, out, tokout);
}